// round 15
// baseline (speedup 1.0000x reference)
#include <cuda_runtime.h>
#include <cuda.h>
#include <cuda_bf16.h>
#include <mma.h>
#include <cstdint>

#define TOKENS 4096
#define DMODEL 1024
#define VOCAB  32000
#define KSEL   128
#define NSAMP  256
#define SSTRIDE 125
#define THR_RANK 14
#define CAP 8192

#if defined(__CUDA_ARCH_FEAT_SM103_ALL) || defined(__CUDA_ARCH_FEAT_SM100_ALL) || \
    defined(__CUDA_ARCH_FEAT_SM101_ALL) || defined(__CUDA_ARCH_SPECIFIC__) || \
    defined(__CUDA_ARCH_FAMILY_SPECIFIC__)
#define TC_PATH 1
#else
#define TC_PATH 0
#endif

// --- GEMM tiling: 128x128 tiles, col-tile PAIRS, 2-stage ring, persistent ---
#define BM 128
#define BN 128
#define BKT 64                     // K elems per smem tile (128B bf16 rows)
#define NKT (DMODEL / BKT)         // 16
#define STAGES 2
#define ATILEB (BM * 128)          // 16KB
#define BTILEB (BN * 128)          // 16KB
#define STAGEB (ATILEB + 2 * BTILEB)   // 48KB: A + B1 + B2
#define SAMPLE_TX (ATILEB + BTILEB)    // sample kernel loads A + one B
#define NCOLT (VOCAB / BN)         // 250 col tiles
#define NPAIRS (NCOLT / 2)         // 125 pairs
#define GRIDY 9                    // 32*9 = 288 persistent CTAs

#define SM_XS     (STAGES * STAGEB)          // 98304
#define SM_BS     (SM_XS + 512)              // bs ping-pong: 2 x 256 floats (2KB)
#define SM_TMEMP  (SM_BS + 2048)
#define SM_MBAR   (SM_TMEMP + 16)
// mbar: free[2]@0,8  full[2]@16,24  done[2]@32,40  epi_free[2]@48,56
#define SM_TOTAL  (SM_MBAR + 96)             // ~100.9KB -> 2 CTAs/SM

// idesc kind::f16 bf16: dtype F32, atype/btype BF16, N=128, M=128
#define MMA_IDESC ((1u<<4)|(1u<<7)|(1u<<10)|((BN/8u)<<17)|((BM/16u)<<24))

// wmma fallback tiling (compile-only on plain sm_103)
#define FBK 32
#define FLDS (FBK + 8)

// Device scratch
static __device__ float g_scr[(size_t)TOKENS * CAP + (size_t)TOKENS * NSAMP];
static __device__ __align__(1024) __nv_bfloat16 g_xb[(size_t)TOKENS * DMODEL];
static __device__ __align__(1024) __nv_bfloat16 g_wb[(size_t)VOCAB * DMODEL];
static __device__ __align__(1024) __nv_bfloat16 g_ws[(size_t)NSAMP * DMODEL];
static __device__ float g_xsq[TOKENS];
static __device__ float g_bsq[VOCAB];
static __device__ float g_bsq_s[NSAMP];
static __device__ float g_thr[TOKENS];
static __device__ unsigned g_ccnt[TOKENS];

// ---------------------------------------------------------------------------
// PTX helpers
// ---------------------------------------------------------------------------
__device__ __forceinline__ uint32_t smem_u32(const void* p) {
    uint32_t a;
    asm("{ .reg .u64 t; cvta.to.shared.u64 t, %1; cvt.u32.u64 %0, t; }" : "=r"(a) : "l"(p));
    return a;
}
__device__ __forceinline__ void cp_async16(uint32_t s, const void* g) {
    asm volatile("cp.async.cg.shared.global [%0], [%1], 16;\n" :: "r"(s), "l"(g));
}
__device__ __forceinline__ void cp_commit() { asm volatile("cp.async.commit_group;\n" ::); }
template <int N>
__device__ __forceinline__ void cp_wait() { asm volatile("cp.async.wait_group %0;\n" :: "n"(N)); }

#if TC_PATH
__device__ __forceinline__ bool elect_one() {
    uint32_t pred;
    asm volatile("{\n\t.reg .pred p;\n\telect.sync _|p, 0xFFFFFFFF;\n\t"
                 "selp.b32 %0, 1, 0, p;\n\t}" : "=r"(pred));
    return pred != 0;
}
__device__ __forceinline__ void mbar_init(uint32_t a, uint32_t cnt) {
    asm volatile("mbarrier.init.shared.b64 [%0], %1;" :: "r"(a), "r"(cnt) : "memory");
}
__device__ __forceinline__ void mbar_inval(uint32_t a) {
    asm volatile("mbarrier.inval.shared.b64 [%0];" :: "r"(a) : "memory");
}
__device__ __forceinline__ void mbar_wait(uint32_t a, uint32_t parity) {
    uint32_t done;
    asm volatile("{\n\t.reg .pred p;\n\t"
                 "mbarrier.try_wait.parity.acquire.cta.shared::cta.b64 p, [%1], %2;\n\t"
                 "selp.b32 %0, 1, 0, p;\n\t}"
                 : "=r"(done) : "r"(a), "r"(parity) : "memory");
    if (!done) {
        asm volatile("{\n\t.reg .pred P1;\n\t"
                     "WL_%=:\n\t"
                     "mbarrier.try_wait.parity.acquire.cta.shared::cta.b64 P1, [%0], %1, 0x989680;\n\t"
                     "@P1 bra.uni WD_%=;\n\t"
                     "bra.uni WL_%=;\n\t"
                     "WD_%=:\n\t}" :: "r"(a), "r"(parity) : "memory");
    }
}
__device__ __forceinline__ void mbar_arrive(uint32_t a) {
    asm volatile("mbarrier.arrive.release.cta.shared::cta.b64 _, [%0];" :: "r"(a) : "memory");
}
__device__ __forceinline__ void mbar_expect_tx(uint32_t a, uint32_t bytes) {
    asm volatile("mbarrier.arrive.expect_tx.shared.b64 _, [%0], %1;"
                 :: "r"(a), "r"(bytes) : "memory");
}
__device__ __forceinline__ void tma_load_2d(uint32_t dst, const void* map,
                                            int cx, int cy, uint32_t mbar) {
    asm volatile("cp.async.bulk.tensor.2d.shared::cta.global.tile.mbarrier::complete_tx::bytes "
                 "[%0], [%1, {%2, %3}], [%4];"
                 :: "r"(dst), "l"(map), "r"(cx), "r"(cy), "r"(mbar) : "memory");
}
__device__ __forceinline__ void tmem_alloc(uint32_t smem_res, uint32_t ncols) {
    asm volatile("tcgen05.alloc.cta_group::1.sync.aligned.shared::cta.b32 [%0], %1;"
                 :: "r"(smem_res), "r"(ncols) : "memory");
}
__device__ __forceinline__ void tmem_dealloc(uint32_t tmem, uint32_t ncols) {
    asm volatile("tcgen05.dealloc.cta_group::1.sync.aligned.b32 %0, %1;" :: "r"(tmem), "r"(ncols));
}
__device__ __forceinline__ void tmem_relinquish() {
    asm volatile("tcgen05.relinquish_alloc_permit.cta_group::1.sync.aligned;");
}
__device__ __forceinline__ void tc_commit(uint32_t mbar) {
    asm volatile("tcgen05.commit.cta_group::1.mbarrier::arrive::one.shared::cluster.b64 [%0];"
                 :: "r"(mbar) : "memory");
}
__device__ __forceinline__ void tc_fence_after() {
    asm volatile("tcgen05.fence::after_thread_sync;" ::: "memory");
}
__device__ __forceinline__ void tc_fence_before() {
    asm volatile("tcgen05.fence::before_thread_sync;" ::: "memory");
}
__device__ __forceinline__ void tc_wait_ld() {
    asm volatile("tcgen05.wait::ld.sync.aligned;" ::: "memory");
}
__device__ __forceinline__ void mma_f16_ss(uint32_t d, uint64_t a, uint64_t b,
                                           uint32_t idesc, uint32_t en) {
    asm volatile("{\n\t.reg .pred p;\n\tsetp.ne.u32 p, %4, 0;\n\t"
                 "tcgen05.mma.cta_group::1.kind::f16 [%0], %1, %2, %3, {%5, %5, %5, %5}, p;\n\t}"
                 :: "r"(d), "l"(a), "l"(b), "r"(idesc), "r"(en), "r"(0u) : "memory");
}
__device__ __forceinline__ void ldtm_x32(uint32_t* r, uint32_t addr) {
    asm volatile("tcgen05.ld.sync.aligned.32x32b.x32.b32 "
                 "{%0, %1, %2, %3, %4, %5, %6, %7, "
                 " %8, %9, %10, %11, %12, %13, %14, %15, "
                 " %16, %17, %18, %19, %20, %21, %22, %23, "
                 " %24, %25, %26, %27, %28, %29, %30, %31}, [%32];"
                 : "=r"(r[0]), "=r"(r[1]), "=r"(r[2]), "=r"(r[3]),
                   "=r"(r[4]), "=r"(r[5]), "=r"(r[6]), "=r"(r[7]),
                   "=r"(r[8]), "=r"(r[9]), "=r"(r[10]), "=r"(r[11]),
                   "=r"(r[12]), "=r"(r[13]), "=r"(r[14]), "=r"(r[15]),
                   "=r"(r[16]), "=r"(r[17]), "=r"(r[18]), "=r"(r[19]),
                   "=r"(r[20]), "=r"(r[21]), "=r"(r[22]), "=r"(r[23]),
                   "=r"(r[24]), "=r"(r[25]), "=r"(r[26]), "=r"(r[27]),
                   "=r"(r[28]), "=r"(r[29]), "=r"(r[30]), "=r"(r[31])
                 : "r"(addr));
}
__device__ __forceinline__ uint64_t make_desc(uint32_t addr) {
    const uint64_t base = (uint64_t(2) << 61) | (uint64_t(1) << 46)
                        | (uint64_t(64) << 32) | (uint64_t(1) << 16);
    return base | ((uint64_t)(addr >> 4) & 0x3FFF);
}
#endif  // TC_PATH

__device__ __forceinline__ unsigned int flip_key(float f) {
    unsigned int u = __float_as_uint(f);
    return u ^ ((u & 0x80000000u) ? 0xFFFFFFFFu : 0x80000000u);
}

// ---------------------------------------------------------------------------
// Fused fp32->bf16 convert + row squared-norm
// ---------------------------------------------------------------------------
__global__ void prep_kernel(const float* __restrict__ src,
                            __nv_bfloat16* __restrict__ dst,
                            float* __restrict__ sq) {
    __shared__ float warp_sums[8];
    const int row = blockIdx.x;
    const int tid = threadIdx.x;
    const float* s = src + (size_t)row * DMODEL;
    __nv_bfloat16* d = dst + (size_t)row * DMODEL;

    float acc = 0.f;
    int j = tid * 4;
    {
        float4 v = *(const float4*)&s[j];
        acc += v.x * v.x + v.y * v.y + v.z * v.z + v.w * v.w;
        __nv_bfloat162 lo = __floats2bfloat162_rn(v.x, v.y);
        __nv_bfloat162 hi = __floats2bfloat162_rn(v.z, v.w);
        uint2 p; p.x = *(uint32_t*)&lo; p.y = *(uint32_t*)&hi;
        *(uint2*)&d[j] = p;
    }
    #pragma unroll
    for (int off = 16; off > 0; off >>= 1)
        acc += __shfl_xor_sync(0xFFFFFFFFu, acc, off);
    if ((tid & 31) == 0) warp_sums[tid >> 5] = acc;
    __syncthreads();
    if (tid == 0) {
        float total = 0.f;
        #pragma unroll
        for (int w = 0; w < 8; w++) total += warp_sums[w];
        sq[row] = total;
    }
}

__global__ void gather_kernel(const __nv_bfloat16* __restrict__ wb,
                              const float* __restrict__ bsq,
                              __nv_bfloat16* __restrict__ ws,
                              float* __restrict__ bsq_s,
                              unsigned* __restrict__ ccnt) {
    const int s = blockIdx.x;
    const int tid = threadIdx.x;
    const int src = s * SSTRIDE;
    ((uint2*)(ws + (size_t)s * DMODEL))[tid] =
        ((const uint2*)(wb + (size_t)src * DMODEL))[tid];
    if (tid == 0) bsq_s[s] = bsq[src];
    if (s < TOKENS / 256) ccnt[s * 256 + tid] = 0;
}

__global__ void thr_kernel(const float* __restrict__ dist_s,
                           float* __restrict__ thr) {
    __shared__ float samp[NSAMP];
    const int t = blockIdx.x;
    const int tid = threadIdx.x;
    samp[tid] = dist_s[(size_t)t * NSAMP + tid];
    __syncthreads();
    for (int k = 2; k <= NSAMP; k <<= 1) {
        for (int j = k >> 1; j > 0; j >>= 1) {
            int ixj = tid ^ j;
            if (ixj > tid) {
                float a = samp[tid], b = samp[ixj];
                bool up = ((tid & k) == 0);
                if ((a > b) == up) { samp[tid] = b; samp[ixj] = a; }
            }
            __syncthreads();
        }
    }
    if (tid == 0) thr[t] = samp[THR_RANK];
}

// ---------------------------------------------------------------------------
// Sample GEMM (non-persistent): writes dist matrix. Loads A + ONE B per stage.
// ---------------------------------------------------------------------------
__global__ void __launch_bounds__(256)
gemm_sample_kernel(const __grid_constant__ CUtensorMap tma_a,
                   const __grid_constant__ CUtensorMap tma_b,
                   const __nv_bfloat16* __restrict__ A,
                   const __nv_bfloat16* __restrict__ B,
                   const float* __restrict__ xsq,
                   const float* __restrict__ bsq,
                   float* __restrict__ C, int ncols) {
    extern __shared__ __align__(1024) char sm[];
    const int tid = threadIdx.x;
    const int warp = tid >> 5;
    const int row0 = blockIdx.x * BM;
    const int col0 = blockIdx.y * BN;

#if TC_PATH
    const uint32_t smem_base = smem_u32(sm);
    float* xs_s = (float*)(sm + SM_XS);
    float* bs_s = (float*)(sm + SM_BS);
    const uint32_t mb_free0 = smem_base + SM_MBAR;        // +s*8
    const uint32_t mb_full0 = smem_base + SM_MBAR + 16;   // +s*8
    const uint32_t mb_done  = smem_base + SM_MBAR + 32;

    if (warp == 0) { tmem_alloc(smem_base + SM_TMEMP, 128); tmem_relinquish(); }
    if (tid == 0) {
        #pragma unroll
        for (int s = 0; s < STAGES; s++) {
            mbar_init(mb_free0 + s * 8, 1);
            mbar_init(mb_full0 + s * 8, 1);
        }
        mbar_init(mb_done, 1);
    }
    if (tid < BM) xs_s[tid] = xsq[row0 + tid];
    else if (tid >= 128 && tid < 256) bs_s[tid - 128] = bsq[col0 + tid - 128];
    __syncthreads();
    uint32_t tmem;
    asm volatile("ld.shared.b32 %0, [%1];" : "=r"(tmem) : "r"(smem_base + SM_TMEMP));

    if (warp == 1 && elect_one()) {
        for (int kt = 0; kt < NKT; kt++) {
            const int s = kt & 1;
            const int w = kt >> 1;
            mbar_wait(mb_free0 + s * 8, (w & 1) ^ 1);
            const uint32_t stage_base = smem_base + s * STAGEB;
            mbar_expect_tx(mb_full0 + s * 8, SAMPLE_TX);
            tma_load_2d(stage_base, &tma_a, kt * BKT, row0, mb_full0 + s * 8);
            tma_load_2d(stage_base + ATILEB, &tma_b, kt * BKT, col0, mb_full0 + s * 8);
        }
    } else if (warp == 0 && elect_one()) {
        for (int kt = 0; kt < NKT; kt++) {
            const int s = kt & 1;
            const int w = kt >> 1;
            mbar_wait(mb_full0 + s * 8, w & 1);
            const uint32_t stage_base = smem_base + s * STAGEB;
            uint64_t ad = make_desc(stage_base);
            uint64_t bd = make_desc(stage_base + ATILEB);
            #pragma unroll
            for (int k = 0; k < 4; k++) {
                uint32_t en = (kt > 0 || k > 0) ? 1u : 0u;
                mma_f16_ss(tmem, ad + k * 2, bd + k * 2, MMA_IDESC, en);
            }
            tc_commit((kt == NKT - 1) ? mb_done : (mb_free0 + s * 8));
        }
    }

    mbar_wait(mb_done, 0);
    tc_fence_after();

    if (tid < 128) {
        const int row = row0 + tid;
        const float base = xs_s[tid];
        #pragma unroll
        for (int c4 = 0; c4 < 4; c4++) {
            uint32_t regs[32];
            ldtm_x32(regs, tmem + c4 * 32);
            tc_wait_ld();
            #pragma unroll
            for (int j = 0; j < 32; j++) {
                float dist = fmaf(-2.0f, __uint_as_float(regs[j]),
                                  base + bs_s[c4 * 32 + j]);
                C[(size_t)row * ncols + col0 + c4 * 32 + j] = dist;
            }
        }
        tc_fence_before();
    }

    __syncthreads();
    if (tid == 0) {
        #pragma unroll
        for (int s = 0; s < STAGES; s++) {
            mbar_inval(mb_free0 + s * 8);
            mbar_inval(mb_full0 + s * 8);
        }
        mbar_inval(mb_done);
    }
    __syncthreads();
    if (warp == 0) tmem_dealloc(tmem, 128);

#else
    using namespace nvcuda;
    __nv_bfloat16* AsBase = (__nv_bfloat16*)sm;
    __nv_bfloat16* BsBase = (__nv_bfloat16*)(sm + 2 * BM * FLDS * 2);
    float* xs_s = (float*)(sm + 4 * BM * FLDS * 2);
    float* bs_s = xs_s + BM;
    float* stg = (float*)sm;
    const int lane = tid & 31;
    const int wm = warp & 1;
    const int wn = warp >> 1;
    if (tid < BM) xs_s[tid] = xsq[row0 + tid];
    if (tid < BN) bs_s[tid] = bsq[col0 + tid];
    __syncthreads();
    wmma::fragment<wmma::accumulator, 16, 16, 16, float> acc[4][2];
    #pragma unroll
    for (int i = 0; i < 4; i++)
        #pragma unroll
        for (int j = 0; j < 2; j++) wmma::fill_fragment(acc[i][j], 0.0f);
    auto asPtr = [&](int st, int r, int c) { return AsBase + (size_t)st * BM * FLDS + r * FLDS + c; };
    auto bsPtr = [&](int st, int r, int c) { return BsBase + (size_t)st * BN * FLDS + r * FLDS + c; };
    auto issue_loads = [&](int st, int k0) {
        #pragma unroll
        for (int i = 0; i < 2; i++) {
            int c = tid + i * 256; int r = c >> 2; int cc = (c & 3) * 8;
            cp_async16(smem_u32(asPtr(st, r, cc)), A + (size_t)(row0 + r) * DMODEL + k0 + cc);
        }
        #pragma unroll
        for (int i = 0; i < 2; i++) {
            int c = tid + i * 256; int r = c >> 2; int cc = (c & 3) * 8;
            cp_async16(smem_u32(bsPtr(st, r, cc)), B + (size_t)(col0 + r) * DMODEL + k0 + cc);
        }
        cp_commit();
    };
    issue_loads(0, 0);
    const int NTF = DMODEL / FBK;
    for (int kt = 0; kt < NTF; kt++) {
        int st = kt & 1;
        if (kt + 1 < NTF) { issue_loads((kt + 1) & 1, (kt + 1) * FBK); cp_wait<1>(); }
        else cp_wait<0>();
        __syncthreads();
        #pragma unroll
        for (int kk = 0; kk < FBK; kk += 16) {
            wmma::fragment<wmma::matrix_a, 16, 16, 16, __nv_bfloat16, wmma::row_major> af[4];
            wmma::fragment<wmma::matrix_b, 16, 16, 16, __nv_bfloat16, wmma::col_major> bf[2];
            #pragma unroll
            for (int mi = 0; mi < 4; mi++)
                wmma::load_matrix_sync(af[mi], asPtr(st, wm * 64 + mi * 16, kk), FLDS);
            #pragma unroll
            for (int ni = 0; ni < 2; ni++)
                wmma::load_matrix_sync(bf[ni], bsPtr(st, wn * 32 + ni * 16, kk), FLDS);
            #pragma unroll
            for (int mi = 0; mi < 4; mi++)
                #pragma unroll
                for (int ni = 0; ni < 2; ni++)
                    wmma::mma_sync(acc[mi][ni], af[mi], bf[ni], acc[mi][ni]);
        }
        __syncthreads();
    }
    float* mystg = stg + warp * 16 * 20;
    #pragma unroll
    for (int mi = 0; mi < 4; mi++)
        #pragma unroll
        for (int ni = 0; ni < 2; ni++) {
            wmma::store_matrix_sync(mystg, acc[mi][ni], 20, wmma::mem_row_major);
            __syncwarp();
            int r = lane >> 1; int cb = (lane & 1) * 8;
            int grow = wm * 64 + mi * 16 + r;
            int gcol = wn * 32 + ni * 16 + cb;
            float base = xs_s[grow];
            float* dst = &C[(size_t)(row0 + grow) * ncols + col0 + gcol];
            #pragma unroll
            for (int c = 0; c < 8; c++)
                dst[c] = fmaf(-2.0f, mystg[r * 20 + cb + c], base + bs_s[gcol + c]);
            __syncwarp();
        }
#endif
}

// ---------------------------------------------------------------------------
// Persistent big GEMM with col-tile PAIRS: one A TMA serves two B tiles.
// TMEM: [h][2 tiles] = 4 x 128 cols. Epilogue overlaps next pair's mainloop.
// ---------------------------------------------------------------------------
__global__ void __launch_bounds__(256)
gemm_persist_kernel(const __grid_constant__ CUtensorMap tma_a,
                    const __grid_constant__ CUtensorMap tma_b,
                    const __nv_bfloat16* __restrict__ A,
                    const __nv_bfloat16* __restrict__ B,
                    const float* __restrict__ xsq,
                    const float* __restrict__ bsq,
                    const float* __restrict__ thr,
                    float* __restrict__ cand,
                    unsigned* __restrict__ ccnt) {
    extern __shared__ __align__(1024) char sm[];
    const int tid = threadIdx.x;
    const int warp = tid >> 5;
    const int row0 = blockIdx.x * BM;

#if TC_PATH
    const uint32_t smem_base = smem_u32(sm);
    float* xs_s = (float*)(sm + SM_XS);
    float* bs2 = (float*)(sm + SM_BS);            // [2][256]
    const uint32_t mb_free0 = smem_base + SM_MBAR;        // +s*8
    const uint32_t mb_full0 = smem_base + SM_MBAR + 16;   // +s*8
    const uint32_t mb_done0 = smem_base + SM_MBAR + 32;   // +h*8
    const uint32_t mb_epi0  = smem_base + SM_MBAR + 48;   // +h*8

    if (warp == 0) { tmem_alloc(smem_base + SM_TMEMP, 512); tmem_relinquish(); }
    if (tid == 0) {
        #pragma unroll
        for (int s = 0; s < STAGES; s++) {
            mbar_init(mb_free0 + s * 8, 1);
            mbar_init(mb_full0 + s * 8, 1);
        }
        #pragma unroll
        for (int h = 0; h < 2; h++) {
            mbar_init(mb_done0 + h * 8, 1);
            mbar_init(mb_epi0 + h * 8, 128);
        }
    }
    if (tid < BM) xs_s[tid] = xsq[row0 + tid];
    __syncthreads();
    uint32_t tmem;
    asm volatile("ld.shared.b32 %0, [%1];" : "=r"(tmem) : "r"(smem_base + SM_TMEMP));

    if (warp == 1 && elect_one()) {
        // ------- producer: one A + two B TMAs per kt -------
        int gkt = 0;
        for (int pi = blockIdx.y; pi < NPAIRS; pi += GRIDY) {
            const int ct0 = pi * 2, ct1 = pi * 2 + 1;
            for (int kt = 0; kt < NKT; kt++, gkt++) {
                const int s = gkt & 1;
                const int w = gkt >> 1;
                mbar_wait(mb_free0 + s * 8, (w & 1) ^ 1);
                const uint32_t stage_base = smem_base + s * STAGEB;
                mbar_expect_tx(mb_full0 + s * 8, STAGEB);
                tma_load_2d(stage_base, &tma_a, kt * BKT, row0, mb_full0 + s * 8);
                tma_load_2d(stage_base + ATILEB, &tma_b, kt * BKT, ct0 * BN, mb_full0 + s * 8);
                tma_load_2d(stage_base + ATILEB + BTILEB, &tma_b, kt * BKT, ct1 * BN, mb_full0 + s * 8);
            }
        }
    } else if (warp == 0 && elect_one()) {
        // ------- MMA driver: 8 dispatches/kt (4 per B tile) -------
        int gkt = 0, ti = 0;
        for (int pi = blockIdx.y; pi < NPAIRS; pi += GRIDY, ti++) {
            const int h = ti & 1;
            const int u = ti >> 1;
            if (ti >= 2) mbar_wait(mb_epi0 + h * 8, (u - 1) & 1);
            const uint32_t dtm0 = tmem + h * 256;
            const uint32_t dtm1 = dtm0 + 128;
            for (int kt = 0; kt < NKT; kt++, gkt++) {
                const int s = gkt & 1;
                const int w = gkt >> 1;
                mbar_wait(mb_full0 + s * 8, w & 1);
                const uint32_t stage_base = smem_base + s * STAGEB;
                uint64_t ad  = make_desc(stage_base);
                uint64_t bd0 = make_desc(stage_base + ATILEB);
                uint64_t bd1 = make_desc(stage_base + ATILEB + BTILEB);
                #pragma unroll
                for (int k = 0; k < 4; k++) {
                    uint32_t en = (kt > 0 || k > 0) ? 1u : 0u;
                    mma_f16_ss(dtm0, ad + k * 2, bd0 + k * 2, MMA_IDESC, en);
                    mma_f16_ss(dtm1, ad + k * 2, bd1 + k * 2, MMA_IDESC, en);
                }
                tc_commit(mb_free0 + s * 8);
                if (kt == NKT - 1) tc_commit(mb_done0 + h * 8);
            }
        }
    }

    // ------- epilogue: threads 128-255, 256 cols (2 tiles) per done -------
    if (tid >= 128) {
        const int e = tid - 128;
        const int row = row0 + e;
        const float base = xs_s[e];
        const float thv = thr[row];
        int ti = 0;
        for (int pi = blockIdx.y; pi < NPAIRS; pi += GRIDY, ti++) {
            const int h = ti & 1;
            const int u = ti >> 1;
            mbar_wait(mb_done0 + h * 8, u & 1);
            tc_fence_after();
            bs2[h * 256 + e] = bsq[(pi * 2) * BN + e];
            bs2[h * 256 + 128 + e] = bsq[(pi * 2 + 1) * BN + e];
            asm volatile("bar.sync 1, 128;" ::: "memory");
            const uint32_t dtm = tmem + h * 256;
            const float* bs = &bs2[h * 256];

            uint32_t masks[8];
            int cnt = 0;
            #pragma unroll
            for (int c4 = 0; c4 < 8; c4++) {
                uint32_t regs[32];
                ldtm_x32(regs, dtm + c4 * 32);
                tc_wait_ld();
                uint32_t mask = 0;
                #pragma unroll
                for (int j = 0; j < 32; j++) {
                    float dist = fmaf(-2.0f, __uint_as_float(regs[j]),
                                      base + bs[c4 * 32 + j]);
                    if (dist <= thv) mask |= (1u << j);
                }
                masks[c4] = mask;
                cnt += __popc(mask);
            }
            unsigned idx = 0;
            if (cnt > 0) idx = atomicAdd(&ccnt[row], (unsigned)cnt);
            #pragma unroll
            for (int c4 = 0; c4 < 8; c4++) {
                uint32_t regs[32];
                ldtm_x32(regs, dtm + c4 * 32);
                tc_wait_ld();
                uint32_t mask = masks[c4];
                #pragma unroll
                for (int j = 0; j < 32; j++) {
                    if ((mask >> j) & 1u) {
                        float dist = fmaf(-2.0f, __uint_as_float(regs[j]),
                                          base + bs[c4 * 32 + j]);
                        if (idx < CAP) cand[(size_t)row * CAP + idx] = dist;
                        idx++;
                    }
                }
            }
            tc_fence_before();
            asm volatile("bar.sync 1, 128;" ::: "memory");
            mbar_arrive(mb_epi0 + h * 8);
        }
    }

    __syncthreads();
    if (tid == 0) {
        #pragma unroll
        for (int s = 0; s < STAGES; s++) {
            mbar_inval(mb_free0 + s * 8);
            mbar_inval(mb_full0 + s * 8);
        }
        #pragma unroll
        for (int h = 0; h < 2; h++) {
            mbar_inval(mb_done0 + h * 8);
            mbar_inval(mb_epi0 + h * 8);
        }
    }
    __syncthreads();
    if (warp == 0) tmem_dealloc(tmem, 512);

#else  // ---------------- WMMA fallback: loop over col tiles ----------------
    using namespace nvcuda;
    __nv_bfloat16* AsBase = (__nv_bfloat16*)sm;
    __nv_bfloat16* BsBase = (__nv_bfloat16*)(sm + 2 * BM * FLDS * 2);
    float* xs_s = (float*)(sm + 4 * BM * FLDS * 2);
    float* bs_s = xs_s + BM;
    float* stg = (float*)sm;
    const int lane = tid & 31;
    const int wm = warp & 1;
    const int wn = warp >> 1;
    if (tid < BM) xs_s[tid] = xsq[row0 + tid];
    __syncthreads();

    for (int ct = blockIdx.y; ct < NCOLT; ct += GRIDY) {
        const int col0 = ct * BN;
        if (tid < BN) bs_s[tid] = bsq[col0 + tid];
        __syncthreads();
        wmma::fragment<wmma::accumulator, 16, 16, 16, float> acc[4][2];
        #pragma unroll
        for (int i = 0; i < 4; i++)
            #pragma unroll
            for (int j = 0; j < 2; j++) wmma::fill_fragment(acc[i][j], 0.0f);
        auto asPtr = [&](int st, int r, int c) { return AsBase + (size_t)st * BM * FLDS + r * FLDS + c; };
        auto bsPtr = [&](int st, int r, int c) { return BsBase + (size_t)st * BN * FLDS + r * FLDS + c; };
        auto issue_loads = [&](int st, int k0) {
            #pragma unroll
            for (int i = 0; i < 2; i++) {
                int c = tid + i * 256; int r = c >> 2; int cc = (c & 3) * 8;
                cp_async16(smem_u32(asPtr(st, r, cc)), A + (size_t)(row0 + r) * DMODEL + k0 + cc);
            }
            #pragma unroll
            for (int i = 0; i < 2; i++) {
                int c = tid + i * 256; int r = c >> 2; int cc = (c & 3) * 8;
                cp_async16(smem_u32(bsPtr(st, r, cc)), B + (size_t)(col0 + r) * DMODEL + k0 + cc);
            }
            cp_commit();
        };
        issue_loads(0, 0);
        const int NTF = DMODEL / FBK;
        for (int kt = 0; kt < NTF; kt++) {
            int st = kt & 1;
            if (kt + 1 < NTF) { issue_loads((kt + 1) & 1, (kt + 1) * FBK); cp_wait<1>(); }
            else cp_wait<0>();
            __syncthreads();
            #pragma unroll
            for (int kk = 0; kk < FBK; kk += 16) {
                wmma::fragment<wmma::matrix_a, 16, 16, 16, __nv_bfloat16, wmma::row_major> af[4];
                wmma::fragment<wmma::matrix_b, 16, 16, 16, __nv_bfloat16, wmma::col_major> bf[2];
                #pragma unroll
                for (int mi = 0; mi < 4; mi++)
                    wmma::load_matrix_sync(af[mi], asPtr(st, wm * 64 + mi * 16, kk), FLDS);
                #pragma unroll
                for (int ni = 0; ni < 2; ni++)
                    wmma::load_matrix_sync(bf[ni], bsPtr(st, wn * 32 + ni * 16, kk), FLDS);
                #pragma unroll
                for (int mi = 0; mi < 4; mi++)
                    #pragma unroll
                    for (int ni = 0; ni < 2; ni++)
                        wmma::mma_sync(acc[mi][ni], af[mi], bf[ni], acc[mi][ni]);
            }
            __syncthreads();
        }
        float* mystg = stg + warp * 16 * 20;
        #pragma unroll
        for (int mi = 0; mi < 4; mi++)
            #pragma unroll
            for (int ni = 0; ni < 2; ni++) {
                wmma::store_matrix_sync(mystg, acc[mi][ni], 20, wmma::mem_row_major);
                __syncwarp();
                int r = lane >> 1; int cb = (lane & 1) * 8;
                int grow = wm * 64 + mi * 16 + r;
                int gcol = wn * 32 + ni * 16 + cb;
                float base = xs_s[grow];
                float vals[8];
                #pragma unroll
                for (int c = 0; c < 8; c++)
                    vals[c] = fmaf(-2.0f, mystg[r * 20 + cb + c], base + bs_s[gcol + c]);
                const int row = row0 + grow;
                const float thv = thr[row];
                int cnt = 0;
                #pragma unroll
                for (int c = 0; c < 8; c++) if (vals[c] <= thv) cnt++;
                unsigned idx = 0;
                if (cnt > 0) idx = atomicAdd(&ccnt[row], (unsigned)cnt);
                #pragma unroll
                for (int c = 0; c < 8; c++) {
                    if (vals[c] <= thv) {
                        if (idx < CAP) cand[(size_t)row * CAP + idx] = vals[c];
                        idx++;
                    }
                }
                __syncwarp();
            }
        __syncthreads();
    }
#endif
}

// ---------------------------------------------------------------------------
// Final selection (uniform-trip-count radix + gather + sort)
// ---------------------------------------------------------------------------
#define FK_SBUF  0
#define FK_HIST  (CAP * 4)
#define FK_BUF2  (FK_HIST + 4096 * 4)
#define FK_CSUM  (FK_BUF2 + 2048 * 4)
#define FK_TOTAL (FK_CSUM + 256 * 4)

__global__ void __launch_bounds__(256) final_kernel(
    const float* __restrict__ cand,
    const unsigned* __restrict__ ccnt,
    float* __restrict__ out) {
    extern __shared__ __align__(16) char fsm[];
    float* sbuf = (float*)(fsm + FK_SBUF);
    uint32_t* hist = (uint32_t*)(fsm + FK_HIST);
    float* buf2 = (float*)(fsm + FK_BUF2);
    uint32_t* csum = (uint32_t*)(fsm + FK_CSUM);
    __shared__ uint32_t sh_bin, sh_less, sh_cnt;

    const int t = blockIdx.x;
    const int tid = threadIdx.x;
    const int lane = tid & 31;
    const float INF = __int_as_float(0x7F800000);

    int n = (int)min(ccnt[t], (unsigned)CAP);
    for (int i = tid; i < n; i += 256)
        sbuf[i] = cand[(size_t)t * CAP + i];
    if (n < KSEL) {
        for (int i = n + tid; i < KSEL; i += 256) sbuf[i] = INF;
        n = KSEL;
    }
    __syncthreads();

    const int n_pad = (n + 255) & ~255;

    unsigned P = 0;
    int lessTotal = 0;
    const int shifts[2] = {20, 8};
    for (int level = 0; level < 2; level++) {
        const int shift = shifts[level];
        const int prevShift = (level > 0) ? shifts[level - 1] : 32;
        for (int i = tid; i < 4096; i += 256) hist[i] = 0;
        __syncthreads();
        for (int base = 0; base < n_pad; base += 256) {
            int i = base + tid;
            int bin = -1;
            if (i < n) {
                unsigned key = flip_key(sbuf[i]);
                bool match = (level == 0) || ((key >> prevShift) == P);
                if (match) bin = (int)((key >> shift) & 4095u);
            }
            unsigned grp = __match_any_sync(0xFFFFFFFFu, bin);
            int leader = __ffs(grp) - 1;
            if (lane == leader && bin >= 0)
                atomicAdd(&hist[bin], __popc(grp));
        }
        __syncthreads();

        unsigned mysum = 0;
        #pragma unroll
        for (int b = 0; b < 16; b++) mysum += hist[tid * 16 + b];
        csum[tid] = mysum;
        __syncthreads();
        #pragma unroll
        for (int off = 1; off < 256; off <<= 1) {
            unsigned v = (tid >= off) ? csum[tid - off] : 0u;
            __syncthreads();
            csum[tid] += v;
            __syncthreads();
        }
        unsigned incl = csum[tid];
        unsigned excl = incl - mysum;
        const unsigned R = (unsigned)(KSEL - lessTotal);
        if (excl < R && R <= incl) {
            unsigned cum = excl;
            for (int b = 0; b < 16; b++) {
                unsigned c = hist[tid * 16 + b];
                if (cum + c >= R) {
                    sh_bin = tid * 16 + b;
                    sh_less = cum;
                    break;
                }
                cum += c;
            }
        }
        __syncthreads();
        P = (level == 0) ? sh_bin : ((P << 12) | sh_bin);
        lessTotal += (int)sh_less;
        __syncthreads();
    }

    if (tid == 0) sh_cnt = 0;
    __syncthreads();
    for (int i = tid; i < n; i += 256) {
        float d = sbuf[i];
        if ((flip_key(d) >> 8) <= P) {
            unsigned p = atomicAdd(&sh_cnt, 1u);
            if (p < 2048) buf2[p] = d;
        }
    }
    __syncthreads();
    int cnt = (int)sh_cnt;

    float* sortbuf;
    int sn;
    if (cnt <= 2048) { sortbuf = buf2; sn = cnt; }
    else             { sortbuf = sbuf; sn = n; }

    int m = KSEL;
    while (m < sn) m <<= 1;
    for (int i = sn + tid; i < m; i += 256) sortbuf[i] = INF;
    __syncthreads();

    for (int ksz = 2; ksz <= m; ksz <<= 1) {
        for (int j2 = ksz >> 1; j2 > 0; j2 >>= 1) {
            for (int i = tid; i < m; i += 256) {
                int ixj = i ^ j2;
                if (ixj > i) {
                    float a = sortbuf[i];
                    float b = sortbuf[ixj];
                    bool up = ((i & ksz) == 0);
                    if ((a > b) == up) { sortbuf[i] = b; sortbuf[ixj] = a; }
                }
            }
            __syncthreads();
        }
    }

    if (tid < KSEL) out[(size_t)t * KSEL + tid] = sortbuf[tid];
}

// ---------------------------------------------------------------------------
// Host: tensor map creation via driver entry point
// ---------------------------------------------------------------------------
typedef CUresult (*PFN_tmapEncode)(
    CUtensorMap*, CUtensorMapDataType, cuuint32_t, void*,
    const cuuint64_t*, const cuuint64_t*, const cuuint32_t*, const cuuint32_t*,
    CUtensorMapInterleave, CUtensorMapSwizzle, CUtensorMapL2promotion,
    CUtensorMapFloatOOBfill);

static PFN_tmapEncode get_encoder() {
    static PFN_tmapEncode fn = nullptr;
    if (!fn) {
        void* p = nullptr;
        cudaDriverEntryPointQueryResult st;
        cudaGetDriverEntryPoint("cuTensorMapEncodeTiled", &p, cudaEnableDefault, &st);
        fn = (PFN_tmapEncode)p;
    }
    return fn;
}

static void make_map(CUtensorMap* map, void* ptr, uint64_t rows, uint32_t box_h) {
    cuuint64_t dims[2] = {DMODEL, rows};
    cuuint64_t strides[1] = {DMODEL * 2};
    cuuint32_t box[2] = {BKT, box_h};
    cuuint32_t elemstr[2] = {1, 1};
    get_encoder()(map, CU_TENSOR_MAP_DATA_TYPE_BFLOAT16, 2, ptr,
                  dims, strides, box, elemstr,
                  CU_TENSOR_MAP_INTERLEAVE_NONE, CU_TENSOR_MAP_SWIZZLE_128B,
                  CU_TENSOR_MAP_L2_PROMOTION_L2_128B,
                  CU_TENSOR_MAP_FLOAT_OOB_FILL_NONE);
}

// ---------------------------------------------------------------------------
// Launch
// ---------------------------------------------------------------------------
extern "C" void kernel_launch(void* const* d_in, const int* in_sizes, int n_in,
                              void* d_out, int out_size) {
    const float* x = (const float*)d_in[0];
    const float* w = (const float*)d_in[1];
    float* out = (float*)d_out;

    float *scr, *xsq, *bsq, *bsq_s, *thr;
    __nv_bfloat16 *xb, *wb, *ws;
    unsigned* ccnt;
    cudaGetSymbolAddress((void**)&scr, g_scr);
    cudaGetSymbolAddress((void**)&xsq, g_xsq);
    cudaGetSymbolAddress((void**)&bsq, g_bsq);
    cudaGetSymbolAddress((void**)&bsq_s, g_bsq_s);
    cudaGetSymbolAddress((void**)&thr, g_thr);
    cudaGetSymbolAddress((void**)&xb, g_xb);
    cudaGetSymbolAddress((void**)&wb, g_wb);
    cudaGetSymbolAddress((void**)&ws, g_ws);
    cudaGetSymbolAddress((void**)&ccnt, g_ccnt);

    float* cand = scr;
    float* dist_s = scr + (size_t)TOKENS * CAP;

    CUtensorMap tma_x, tma_w, tma_ws;
    make_map(&tma_x, xb, TOKENS, BM);
    make_map(&tma_w, wb, VOCAB, BN);
    make_map(&tma_ws, ws, NSAMP, BN);

    prep_kernel<<<TOKENS, 256>>>(x, xb, xsq);
    prep_kernel<<<VOCAB, 256>>>(w, wb, bsq);
    gather_kernel<<<NSAMP, 256>>>(wb, bsq, ws, bsq_s, ccnt);

    cudaFuncSetAttribute(gemm_sample_kernel,
                         cudaFuncAttributeMaxDynamicSharedMemorySize, SM_TOTAL);
    cudaFuncSetAttribute(gemm_persist_kernel,
                         cudaFuncAttributeMaxDynamicSharedMemorySize, SM_TOTAL);
    cudaFuncSetAttribute(final_kernel,
                         cudaFuncAttributeMaxDynamicSharedMemorySize, FK_TOTAL);

    // Sample GEMM: [4096 x 256]
    gemm_sample_kernel<<<dim3(TOKENS / BM, NSAMP / BN), 256, SM_TOTAL>>>(
        tma_x, tma_ws, xb, ws, xsq, bsq_s, dist_s, NSAMP);

    thr_kernel<<<TOKENS, 256>>>(dist_s, thr);

    // Persistent big GEMM over col-tile pairs
    gemm_persist_kernel<<<dim3(TOKENS / BM, GRIDY), 256, SM_TOTAL>>>(
        tma_x, tma_w, xb, wb, xsq, bsq, thr, cand, ccnt);

    final_kernel<<<TOKENS, 256, FK_TOTAL>>>(cand, ccnt, out);
}

// round 16
// speedup vs baseline: 1.0588x; 1.0588x over previous
#include <cuda_runtime.h>
#include <cuda.h>
#include <cuda_bf16.h>
#include <mma.h>
#include <cstdint>

#define TOKENS 4096
#define DMODEL 1024
#define VOCAB  32000
#define KSEL   128
#define NSAMP  256
#define SSTRIDE 125
#define THR_RANK 14
#define CAP 8192

#if defined(__CUDA_ARCH_FEAT_SM103_ALL) || defined(__CUDA_ARCH_FEAT_SM100_ALL) || \
    defined(__CUDA_ARCH_FEAT_SM101_ALL) || defined(__CUDA_ARCH_SPECIFIC__) || \
    defined(__CUDA_ARCH_FAMILY_SPECIFIC__)
#define TC_PATH 1
#else
#define TC_PATH 0
#endif

// ------- GEMM tiling: 128x128 tile, 3-stage smem ring, persistent CTAs -------
#define BM 128
#define BN 128
#define BKT 64                     // K elems per smem tile (128B bf16 rows)
#define NKT (DMODEL / BKT)         // 16
#define STAGES 3
#define ATILEB (BM * 128)          // 16KB
#define BTILEB (BN * 128)          // 16KB
#define STAGEB (ATILEB + BTILEB)   // 32KB
#define NCOLT (VOCAB / BN)         // 250 col tiles
#define GRIDY 9                    // 32*9 = 288 persistent CTAs
#define NACC 4                     // TMEM accumulator ring depth (4 x 128 cols)

#define SM_XS     (STAGES * STAGEB)          // 98304
#define SM_BS     (SM_XS + 512)              // bs ring: 4 x 128 floats (2KB)
#define SM_TMEMP  (SM_BS + 2048)
#define SM_MBAR   (SM_TMEMP + 16)
// mbar: free[3]@0,8,16  full[3]@24,32,40  done[4]@48..72  epi_free[4]@80..104
#define SM_TOTAL  (SM_MBAR + 128)            // ~100.6KB -> 2 CTAs/SM

// idesc kind::f16 bf16: dtype F32, atype/btype BF16, N=128, M=128
#define MMA_IDESC ((1u<<4)|(1u<<7)|(1u<<10)|((BN/8u)<<17)|((BM/16u)<<24))

// wmma fallback tiling (compile-only on plain sm_103)
#define FBK 32
#define FLDS (FBK + 8)

// Device scratch
static __device__ float g_scr[(size_t)TOKENS * CAP + (size_t)TOKENS * NSAMP];
static __device__ __align__(1024) __nv_bfloat16 g_xb[(size_t)TOKENS * DMODEL];
static __device__ __align__(1024) __nv_bfloat16 g_wb[(size_t)VOCAB * DMODEL];
static __device__ __align__(1024) __nv_bfloat16 g_ws[(size_t)NSAMP * DMODEL];
static __device__ float g_xsq[TOKENS];
static __device__ float g_bsq[VOCAB];
static __device__ float g_bsq_s[NSAMP];
static __device__ float g_thr[TOKENS];
static __device__ unsigned g_ccnt[TOKENS];

// ---------------------------------------------------------------------------
// PTX helpers
// ---------------------------------------------------------------------------
__device__ __forceinline__ uint32_t smem_u32(const void* p) {
    uint32_t a;
    asm("{ .reg .u64 t; cvta.to.shared.u64 t, %1; cvt.u32.u64 %0, t; }" : "=r"(a) : "l"(p));
    return a;
}
__device__ __forceinline__ void cp_async16(uint32_t s, const void* g) {
    asm volatile("cp.async.cg.shared.global [%0], [%1], 16;\n" :: "r"(s), "l"(g));
}
__device__ __forceinline__ void cp_commit() { asm volatile("cp.async.commit_group;\n" ::); }
template <int N>
__device__ __forceinline__ void cp_wait() { asm volatile("cp.async.wait_group %0;\n" :: "n"(N)); }

#if TC_PATH
__device__ __forceinline__ bool elect_one() {
    uint32_t pred;
    asm volatile("{\n\t.reg .pred p;\n\telect.sync _|p, 0xFFFFFFFF;\n\t"
                 "selp.b32 %0, 1, 0, p;\n\t}" : "=r"(pred));
    return pred != 0;
}
__device__ __forceinline__ void mbar_init(uint32_t a, uint32_t cnt) {
    asm volatile("mbarrier.init.shared.b64 [%0], %1;" :: "r"(a), "r"(cnt) : "memory");
}
__device__ __forceinline__ void mbar_inval(uint32_t a) {
    asm volatile("mbarrier.inval.shared.b64 [%0];" :: "r"(a) : "memory");
}
__device__ __forceinline__ void mbar_wait(uint32_t a, uint32_t parity) {
    uint32_t done;
    asm volatile("{\n\t.reg .pred p;\n\t"
                 "mbarrier.try_wait.parity.acquire.cta.shared::cta.b64 p, [%1], %2;\n\t"
                 "selp.b32 %0, 1, 0, p;\n\t}"
                 : "=r"(done) : "r"(a), "r"(parity) : "memory");
    if (!done) {
        asm volatile("{\n\t.reg .pred P1;\n\t"
                     "WL_%=:\n\t"
                     "mbarrier.try_wait.parity.acquire.cta.shared::cta.b64 P1, [%0], %1, 0x989680;\n\t"
                     "@P1 bra.uni WD_%=;\n\t"
                     "bra.uni WL_%=;\n\t"
                     "WD_%=:\n\t}" :: "r"(a), "r"(parity) : "memory");
    }
}
__device__ __forceinline__ void mbar_arrive(uint32_t a) {
    asm volatile("mbarrier.arrive.release.cta.shared::cta.b64 _, [%0];" :: "r"(a) : "memory");
}
__device__ __forceinline__ void mbar_expect_tx(uint32_t a, uint32_t bytes) {
    asm volatile("mbarrier.arrive.expect_tx.shared.b64 _, [%0], %1;"
                 :: "r"(a), "r"(bytes) : "memory");
}
__device__ __forceinline__ void tma_load_2d(uint32_t dst, const void* map,
                                            int cx, int cy, uint32_t mbar) {
    asm volatile("cp.async.bulk.tensor.2d.shared::cta.global.tile.mbarrier::complete_tx::bytes "
                 "[%0], [%1, {%2, %3}], [%4];"
                 :: "r"(dst), "l"(map), "r"(cx), "r"(cy), "r"(mbar) : "memory");
}
__device__ __forceinline__ void tmem_alloc(uint32_t smem_res, uint32_t ncols) {
    asm volatile("tcgen05.alloc.cta_group::1.sync.aligned.shared::cta.b32 [%0], %1;"
                 :: "r"(smem_res), "r"(ncols) : "memory");
}
__device__ __forceinline__ void tmem_dealloc(uint32_t tmem, uint32_t ncols) {
    asm volatile("tcgen05.dealloc.cta_group::1.sync.aligned.b32 %0, %1;" :: "r"(tmem), "r"(ncols));
}
__device__ __forceinline__ void tmem_relinquish() {
    asm volatile("tcgen05.relinquish_alloc_permit.cta_group::1.sync.aligned;");
}
__device__ __forceinline__ void tc_commit(uint32_t mbar) {
    asm volatile("tcgen05.commit.cta_group::1.mbarrier::arrive::one.shared::cluster.b64 [%0];"
                 :: "r"(mbar) : "memory");
}
__device__ __forceinline__ void tc_fence_after() {
    asm volatile("tcgen05.fence::after_thread_sync;" ::: "memory");
}
__device__ __forceinline__ void tc_fence_before() {
    asm volatile("tcgen05.fence::before_thread_sync;" ::: "memory");
}
__device__ __forceinline__ void tc_wait_ld() {
    asm volatile("tcgen05.wait::ld.sync.aligned;" ::: "memory");
}
__device__ __forceinline__ void mma_f16_ss(uint32_t d, uint64_t a, uint64_t b,
                                           uint32_t idesc, uint32_t en) {
    asm volatile("{\n\t.reg .pred p;\n\tsetp.ne.u32 p, %4, 0;\n\t"
                 "tcgen05.mma.cta_group::1.kind::f16 [%0], %1, %2, %3, {%5, %5, %5, %5}, p;\n\t}"
                 :: "r"(d), "l"(a), "l"(b), "r"(idesc), "r"(en), "r"(0u) : "memory");
}
__device__ __forceinline__ void ldtm_x32(uint32_t* r, uint32_t addr) {
    asm volatile("tcgen05.ld.sync.aligned.32x32b.x32.b32 "
                 "{%0, %1, %2, %3, %4, %5, %6, %7, "
                 " %8, %9, %10, %11, %12, %13, %14, %15, "
                 " %16, %17, %18, %19, %20, %21, %22, %23, "
                 " %24, %25, %26, %27, %28, %29, %30, %31}, [%32];"
                 : "=r"(r[0]), "=r"(r[1]), "=r"(r[2]), "=r"(r[3]),
                   "=r"(r[4]), "=r"(r[5]), "=r"(r[6]), "=r"(r[7]),
                   "=r"(r[8]), "=r"(r[9]), "=r"(r[10]), "=r"(r[11]),
                   "=r"(r[12]), "=r"(r[13]), "=r"(r[14]), "=r"(r[15]),
                   "=r"(r[16]), "=r"(r[17]), "=r"(r[18]), "=r"(r[19]),
                   "=r"(r[20]), "=r"(r[21]), "=r"(r[22]), "=r"(r[23]),
                   "=r"(r[24]), "=r"(r[25]), "=r"(r[26]), "=r"(r[27]),
                   "=r"(r[28]), "=r"(r[29]), "=r"(r[30]), "=r"(r[31])
                 : "r"(addr));
}
__device__ __forceinline__ uint64_t make_desc(uint32_t addr) {
    const uint64_t base = (uint64_t(2) << 61) | (uint64_t(1) << 46)
                        | (uint64_t(64) << 32) | (uint64_t(1) << 16);
    return base | ((uint64_t)(addr >> 4) & 0x3FFF);
}
#endif  // TC_PATH

__device__ __forceinline__ unsigned int flip_key(float f) {
    unsigned int u = __float_as_uint(f);
    return u ^ ((u & 0x80000000u) ? 0xFFFFFFFFu : 0x80000000u);
}

// ---------------------------------------------------------------------------
// Fused fp32->bf16 convert + row squared-norm
// ---------------------------------------------------------------------------
__global__ void prep_kernel(const float* __restrict__ src,
                            __nv_bfloat16* __restrict__ dst,
                            float* __restrict__ sq) {
    __shared__ float warp_sums[8];
    const int row = blockIdx.x;
    const int tid = threadIdx.x;
    const float* s = src + (size_t)row * DMODEL;
    __nv_bfloat16* d = dst + (size_t)row * DMODEL;

    float acc = 0.f;
    int j = tid * 4;
    {
        float4 v = *(const float4*)&s[j];
        acc += v.x * v.x + v.y * v.y + v.z * v.z + v.w * v.w;
        __nv_bfloat162 lo = __floats2bfloat162_rn(v.x, v.y);
        __nv_bfloat162 hi = __floats2bfloat162_rn(v.z, v.w);
        uint2 p; p.x = *(uint32_t*)&lo; p.y = *(uint32_t*)&hi;
        *(uint2*)&d[j] = p;
    }
    #pragma unroll
    for (int off = 16; off > 0; off >>= 1)
        acc += __shfl_xor_sync(0xFFFFFFFFu, acc, off);
    if ((tid & 31) == 0) warp_sums[tid >> 5] = acc;
    __syncthreads();
    if (tid == 0) {
        float total = 0.f;
        #pragma unroll
        for (int w = 0; w < 8; w++) total += warp_sums[w];
        sq[row] = total;
    }
}

__global__ void gather_kernel(const __nv_bfloat16* __restrict__ wb,
                              const float* __restrict__ bsq,
                              __nv_bfloat16* __restrict__ ws,
                              float* __restrict__ bsq_s,
                              unsigned* __restrict__ ccnt) {
    const int s = blockIdx.x;
    const int tid = threadIdx.x;
    const int src = s * SSTRIDE;
    ((uint2*)(ws + (size_t)s * DMODEL))[tid] =
        ((const uint2*)(wb + (size_t)src * DMODEL))[tid];
    if (tid == 0) bsq_s[s] = bsq[src];
    if (s < TOKENS / 256) ccnt[s * 256 + tid] = 0;
}

__global__ void thr_kernel(const float* __restrict__ dist_s,
                           float* __restrict__ thr) {
    __shared__ float samp[NSAMP];
    const int t = blockIdx.x;
    const int tid = threadIdx.x;
    samp[tid] = dist_s[(size_t)t * NSAMP + tid];
    __syncthreads();
    for (int k = 2; k <= NSAMP; k <<= 1) {
        for (int j = k >> 1; j > 0; j >>= 1) {
            int ixj = tid ^ j;
            if (ixj > tid) {
                float a = samp[tid], b = samp[ixj];
                bool up = ((tid & k) == 0);
                if ((a > b) == up) { samp[tid] = b; samp[ixj] = a; }
            }
            __syncthreads();
        }
    }
    if (tid == 0) thr[t] = samp[THR_RANK];
}

// ---------------------------------------------------------------------------
// Sample GEMM (non-persistent): writes dist matrix.
// ---------------------------------------------------------------------------
__global__ void __launch_bounds__(256)
gemm_sample_kernel(const __grid_constant__ CUtensorMap tma_a,
                   const __grid_constant__ CUtensorMap tma_b,
                   const __nv_bfloat16* __restrict__ A,
                   const __nv_bfloat16* __restrict__ B,
                   const float* __restrict__ xsq,
                   const float* __restrict__ bsq,
                   float* __restrict__ C, int ncols) {
    extern __shared__ __align__(1024) char sm[];
    const int tid = threadIdx.x;
    const int warp = tid >> 5;
    const int row0 = blockIdx.x * BM;
    const int col0 = blockIdx.y * BN;

#if TC_PATH
    const uint32_t smem_base = smem_u32(sm);
    float* xs_s = (float*)(sm + SM_XS);
    float* bs_s = (float*)(sm + SM_BS);
    const uint32_t mb_free0 = smem_base + SM_MBAR;
    const uint32_t mb_full0 = smem_base + SM_MBAR + 24;
    const uint32_t mb_done  = smem_base + SM_MBAR + 48;

    if (warp == 0) { tmem_alloc(smem_base + SM_TMEMP, 128); tmem_relinquish(); }
    if (tid == 0) {
        #pragma unroll
        for (int s = 0; s < STAGES; s++) {
            mbar_init(mb_free0 + s * 8, 1);
            mbar_init(mb_full0 + s * 8, 1);
        }
        mbar_init(mb_done, 1);
    }
    if (tid < BM) xs_s[tid] = xsq[row0 + tid];
    else if (tid >= 128 && tid < 256) bs_s[tid - 128] = bsq[col0 + tid - 128];
    __syncthreads();
    uint32_t tmem;
    asm volatile("ld.shared.b32 %0, [%1];" : "=r"(tmem) : "r"(smem_base + SM_TMEMP));

    if (warp == 1 && elect_one()) {
        for (int kt = 0; kt < NKT; kt++) {
            const int s = kt % STAGES;
            const int w = kt / STAGES;
            mbar_wait(mb_free0 + s * 8, (w & 1) ^ 1);
            const uint32_t stage_base = smem_base + s * STAGEB;
            mbar_expect_tx(mb_full0 + s * 8, STAGEB);
            tma_load_2d(stage_base, &tma_a, kt * BKT, row0, mb_full0 + s * 8);
            tma_load_2d(stage_base + ATILEB, &tma_b, kt * BKT, col0, mb_full0 + s * 8);
        }
    } else if (warp == 0 && elect_one()) {
        for (int kt = 0; kt < NKT; kt++) {
            const int s = kt % STAGES;
            const int w = kt / STAGES;
            mbar_wait(mb_full0 + s * 8, w & 1);
            const uint32_t stage_base = smem_base + s * STAGEB;
            uint64_t ad = make_desc(stage_base);
            uint64_t bd = make_desc(stage_base + ATILEB);
            #pragma unroll
            for (int k = 0; k < 4; k++) {
                uint32_t en = (kt > 0 || k > 0) ? 1u : 0u;
                mma_f16_ss(tmem, ad + k * 2, bd + k * 2, MMA_IDESC, en);
            }
            tc_commit((kt == NKT - 1) ? mb_done : (mb_free0 + s * 8));
        }
    }

    mbar_wait(mb_done, 0);
    tc_fence_after();

    if (tid < 128) {
        const int row = row0 + tid;
        const float base = xs_s[tid];
        #pragma unroll
        for (int c4 = 0; c4 < 4; c4++) {
            uint32_t regs[32];
            ldtm_x32(regs, tmem + c4 * 32);
            tc_wait_ld();
            #pragma unroll
            for (int j = 0; j < 32; j++) {
                float dist = fmaf(-2.0f, __uint_as_float(regs[j]),
                                  base + bs_s[c4 * 32 + j]);
                C[(size_t)row * ncols + col0 + c4 * 32 + j] = dist;
            }
        }
        tc_fence_before();
    }

    __syncthreads();
    if (tid == 0) {
        #pragma unroll
        for (int s = 0; s < STAGES; s++) {
            mbar_inval(mb_free0 + s * 8);
            mbar_inval(mb_full0 + s * 8);
        }
        mbar_inval(mb_done);
    }
    __syncthreads();
    if (warp == 0) tmem_dealloc(tmem, 128);

#else
    using namespace nvcuda;
    __nv_bfloat16* AsBase = (__nv_bfloat16*)sm;
    __nv_bfloat16* BsBase = (__nv_bfloat16*)(sm + 2 * BM * FLDS * 2);
    float* xs_s = (float*)(sm + 4 * BM * FLDS * 2);
    float* bs_s = xs_s + BM;
    float* stg = (float*)sm;
    const int lane = tid & 31;
    const int wm = warp & 1;
    const int wn = warp >> 1;
    if (tid < BM) xs_s[tid] = xsq[row0 + tid];
    if (tid < BN) bs_s[tid] = bsq[col0 + tid];
    __syncthreads();
    wmma::fragment<wmma::accumulator, 16, 16, 16, float> acc[4][2];
    #pragma unroll
    for (int i = 0; i < 4; i++)
        #pragma unroll
        for (int j = 0; j < 2; j++) wmma::fill_fragment(acc[i][j], 0.0f);
    auto asPtr = [&](int st, int r, int c) { return AsBase + (size_t)st * BM * FLDS + r * FLDS + c; };
    auto bsPtr = [&](int st, int r, int c) { return BsBase + (size_t)st * BN * FLDS + r * FLDS + c; };
    auto issue_loads = [&](int st, int k0) {
        #pragma unroll
        for (int i = 0; i < 2; i++) {
            int c = tid + i * 256; int r = c >> 2; int cc = (c & 3) * 8;
            cp_async16(smem_u32(asPtr(st, r, cc)), A + (size_t)(row0 + r) * DMODEL + k0 + cc);
        }
        #pragma unroll
        for (int i = 0; i < 2; i++) {
            int c = tid + i * 256; int r = c >> 2; int cc = (c & 3) * 8;
            cp_async16(smem_u32(bsPtr(st, r, cc)), B + (size_t)(col0 + r) * DMODEL + k0 + cc);
        }
        cp_commit();
    };
    issue_loads(0, 0);
    const int NTF = DMODEL / FBK;
    for (int kt = 0; kt < NTF; kt++) {
        int st = kt & 1;
        if (kt + 1 < NTF) { issue_loads((kt + 1) & 1, (kt + 1) * FBK); cp_wait<1>(); }
        else cp_wait<0>();
        __syncthreads();
        #pragma unroll
        for (int kk = 0; kk < FBK; kk += 16) {
            wmma::fragment<wmma::matrix_a, 16, 16, 16, __nv_bfloat16, wmma::row_major> af[4];
            wmma::fragment<wmma::matrix_b, 16, 16, 16, __nv_bfloat16, wmma::col_major> bf[2];
            #pragma unroll
            for (int mi = 0; mi < 4; mi++)
                wmma::load_matrix_sync(af[mi], asPtr(st, wm * 64 + mi * 16, kk), FLDS);
            #pragma unroll
            for (int ni = 0; ni < 2; ni++)
                wmma::load_matrix_sync(bf[ni], bsPtr(st, wn * 32 + ni * 16, kk), FLDS);
            #pragma unroll
            for (int mi = 0; mi < 4; mi++)
                #pragma unroll
                for (int ni = 0; ni < 2; ni++)
                    wmma::mma_sync(acc[mi][ni], af[mi], bf[ni], acc[mi][ni]);
        }
        __syncthreads();
    }
    float* mystg = stg + warp * 16 * 20;
    #pragma unroll
    for (int mi = 0; mi < 4; mi++)
        #pragma unroll
        for (int ni = 0; ni < 2; ni++) {
            wmma::store_matrix_sync(mystg, acc[mi][ni], 20, wmma::mem_row_major);
            __syncwarp();
            int r = lane >> 1; int cb = (lane & 1) * 8;
            int grow = wm * 64 + mi * 16 + r;
            int gcol = wn * 32 + ni * 16 + cb;
            float base = xs_s[grow];
            float* dst = &C[(size_t)(row0 + grow) * ncols + col0 + gcol];
            #pragma unroll
            for (int c = 0; c < 8; c++)
                dst[c] = fmaf(-2.0f, mystg[r * 20 + cb + c], base + bs_s[gcol + c]);
            __syncwarp();
        }
#endif
}

// ---------------------------------------------------------------------------
// Persistent big GEMM: 288 CTAs walk col tiles; QUAD-buffered TMEM accumulator
// ring (4 x 128 cols); epilogue (warps 4-7) lags up to 3 tiles behind MMA.
// ---------------------------------------------------------------------------
__global__ void __launch_bounds__(256)
gemm_persist_kernel(const __grid_constant__ CUtensorMap tma_a,
                    const __grid_constant__ CUtensorMap tma_b,
                    const __nv_bfloat16* __restrict__ A,
                    const __nv_bfloat16* __restrict__ B,
                    const float* __restrict__ xsq,
                    const float* __restrict__ bsq,
                    const float* __restrict__ thr,
                    float* __restrict__ cand,
                    unsigned* __restrict__ ccnt) {
    extern __shared__ __align__(1024) char sm[];
    const int tid = threadIdx.x;
    const int warp = tid >> 5;
    const int row0 = blockIdx.x * BM;

#if TC_PATH
    const uint32_t smem_base = smem_u32(sm);
    float* xs_s = (float*)(sm + SM_XS);
    float* bs4 = (float*)(sm + SM_BS);            // [NACC][128]
    const uint32_t mb_free0 = smem_base + SM_MBAR;        // +s*8
    const uint32_t mb_full0 = smem_base + SM_MBAR + 24;   // +s*8
    const uint32_t mb_done0 = smem_base + SM_MBAR + 48;   // +h*8 (4 slots)
    const uint32_t mb_epi0  = smem_base + SM_MBAR + 80;   // +h*8 (4 slots)

    if (warp == 0) { tmem_alloc(smem_base + SM_TMEMP, 512); tmem_relinquish(); }
    if (tid == 0) {
        #pragma unroll
        for (int s = 0; s < STAGES; s++) {
            mbar_init(mb_free0 + s * 8, 1);
            mbar_init(mb_full0 + s * 8, 1);
        }
        #pragma unroll
        for (int h = 0; h < NACC; h++) {
            mbar_init(mb_done0 + h * 8, 1);
            mbar_init(mb_epi0 + h * 8, 128);
        }
    }
    if (tid < BM) xs_s[tid] = xsq[row0 + tid];
    __syncthreads();
    uint32_t tmem;
    asm volatile("ld.shared.b32 %0, [%1];" : "=r"(tmem) : "r"(smem_base + SM_TMEMP));

    if (warp == 1 && elect_one()) {
        // ---------------- producer: TMA over all tiles ----------------
        int gkt = 0;
        for (int ct = blockIdx.y; ct < NCOLT; ct += GRIDY) {
            for (int kt = 0; kt < NKT; kt++, gkt++) {
                const int s = gkt % STAGES;
                const int w = gkt / STAGES;
                mbar_wait(mb_free0 + s * 8, (w & 1) ^ 1);
                const uint32_t stage_base = smem_base + s * STAGEB;
                mbar_expect_tx(mb_full0 + s * 8, STAGEB);
                tma_load_2d(stage_base, &tma_a, kt * BKT, row0, mb_full0 + s * 8);
                tma_load_2d(stage_base + ATILEB, &tma_b, kt * BKT, ct * BN, mb_full0 + s * 8);
            }
        }
    } else if (warp == 0 && elect_one()) {
        // ---------------- MMA driver ----------------
        int gkt = 0, ti = 0;
        for (int ct = blockIdx.y; ct < NCOLT; ct += GRIDY, ti++) {
            const int h = ti & (NACC - 1);
            const int u = ti / NACC;
            if (ti >= NACC) mbar_wait(mb_epi0 + h * 8, (u - 1) & 1);
            const uint32_t dtm = tmem + h * 128;
            for (int kt = 0; kt < NKT; kt++, gkt++) {
                const int s = gkt % STAGES;
                const int w = gkt / STAGES;
                mbar_wait(mb_full0 + s * 8, w & 1);
                const uint32_t stage_base = smem_base + s * STAGEB;
                uint64_t ad = make_desc(stage_base);
                uint64_t bd = make_desc(stage_base + ATILEB);
                #pragma unroll
                for (int k = 0; k < 4; k++) {
                    uint32_t en = (kt > 0 || k > 0) ? 1u : 0u;
                    mma_f16_ss(dtm, ad + k * 2, bd + k * 2, MMA_IDESC, en);
                }
                tc_commit(mb_free0 + s * 8);
                if (kt == NKT - 1) tc_commit(mb_done0 + h * 8);
            }
        }
    }

    // ---------------- epilogue: threads 128-255 (warps 4-7) ----------------
    if (tid >= 128) {
        const int e = tid - 128;
        const int row = row0 + e;
        const float base = xs_s[e];
        const float thv = thr[row];
        int ti = 0;
        for (int ct = blockIdx.y; ct < NCOLT; ct += GRIDY, ti++) {
            const int h = ti & (NACC - 1);
            const int u = ti / NACC;
            mbar_wait(mb_done0 + h * 8, u & 1);
            tc_fence_after();
            bs4[h * 128 + e] = bsq[ct * BN + e];
            asm volatile("bar.sync 1, 128;" ::: "memory");
            const uint32_t dtm = tmem + h * 128;
            const float* bs = &bs4[h * 128];

            uint32_t masks[4];
            int cnt = 0;
            #pragma unroll
            for (int c4 = 0; c4 < 4; c4++) {
                uint32_t regs[32];
                ldtm_x32(regs, dtm + c4 * 32);
                tc_wait_ld();
                uint32_t mask = 0;
                #pragma unroll
                for (int j = 0; j < 32; j++) {
                    float dist = fmaf(-2.0f, __uint_as_float(regs[j]),
                                      base + bs[c4 * 32 + j]);
                    if (dist <= thv) mask |= (1u << j);
                }
                masks[c4] = mask;
                cnt += __popc(mask);
            }
            unsigned idx = 0;
            if (cnt > 0) idx = atomicAdd(&ccnt[row], (unsigned)cnt);
            #pragma unroll
            for (int c4 = 0; c4 < 4; c4++) {
                uint32_t regs[32];
                ldtm_x32(regs, dtm + c4 * 32);
                tc_wait_ld();
                uint32_t mask = masks[c4];
                #pragma unroll
                for (int j = 0; j < 32; j++) {
                    if ((mask >> j) & 1u) {
                        float dist = fmaf(-2.0f, __uint_as_float(regs[j]),
                                          base + bs[c4 * 32 + j]);
                        if (idx < CAP) cand[(size_t)row * CAP + idx] = dist;
                        idx++;
                    }
                }
            }
            tc_fence_before();
            asm volatile("bar.sync 1, 128;" ::: "memory");
            mbar_arrive(mb_epi0 + h * 8);
        }
    }

    __syncthreads();
    if (tid == 0) {
        #pragma unroll
        for (int s = 0; s < STAGES; s++) {
            mbar_inval(mb_free0 + s * 8);
            mbar_inval(mb_full0 + s * 8);
        }
        #pragma unroll
        for (int h = 0; h < NACC; h++) {
            mbar_inval(mb_done0 + h * 8);
            mbar_inval(mb_epi0 + h * 8);
        }
    }
    __syncthreads();
    if (warp == 0) tmem_dealloc(tmem, 512);

#else  // ---------------- WMMA fallback: loop over col tiles ----------------
    using namespace nvcuda;
    __nv_bfloat16* AsBase = (__nv_bfloat16*)sm;
    __nv_bfloat16* BsBase = (__nv_bfloat16*)(sm + 2 * BM * FLDS * 2);
    float* xs_s = (float*)(sm + 4 * BM * FLDS * 2);
    float* bs_s = xs_s + BM;
    float* stg = (float*)sm;
    const int lane = tid & 31;
    const int wm = warp & 1;
    const int wn = warp >> 1;
    if (tid < BM) xs_s[tid] = xsq[row0 + tid];
    __syncthreads();

    for (int ct = blockIdx.y; ct < NCOLT; ct += GRIDY) {
        const int col0 = ct * BN;
        if (tid < BN) bs_s[tid] = bsq[col0 + tid];
        __syncthreads();
        wmma::fragment<wmma::accumulator, 16, 16, 16, float> acc[4][2];
        #pragma unroll
        for (int i = 0; i < 4; i++)
            #pragma unroll
            for (int j = 0; j < 2; j++) wmma::fill_fragment(acc[i][j], 0.0f);
        auto asPtr = [&](int st, int r, int c) { return AsBase + (size_t)st * BM * FLDS + r * FLDS + c; };
        auto bsPtr = [&](int st, int r, int c) { return BsBase + (size_t)st * BN * FLDS + r * FLDS + c; };
        auto issue_loads = [&](int st, int k0) {
            #pragma unroll
            for (int i = 0; i < 2; i++) {
                int c = tid + i * 256; int r = c >> 2; int cc = (c & 3) * 8;
                cp_async16(smem_u32(asPtr(st, r, cc)), A + (size_t)(row0 + r) * DMODEL + k0 + cc);
            }
            #pragma unroll
            for (int i = 0; i < 2; i++) {
                int c = tid + i * 256; int r = c >> 2; int cc = (c & 3) * 8;
                cp_async16(smem_u32(bsPtr(st, r, cc)), B + (size_t)(col0 + r) * DMODEL + k0 + cc);
            }
            cp_commit();
        };
        issue_loads(0, 0);
        const int NTF = DMODEL / FBK;
        for (int kt = 0; kt < NTF; kt++) {
            int st = kt & 1;
            if (kt + 1 < NTF) { issue_loads((kt + 1) & 1, (kt + 1) * FBK); cp_wait<1>(); }
            else cp_wait<0>();
            __syncthreads();
            #pragma unroll
            for (int kk = 0; kk < FBK; kk += 16) {
                wmma::fragment<wmma::matrix_a, 16, 16, 16, __nv_bfloat16, wmma::row_major> af[4];
                wmma::fragment<wmma::matrix_b, 16, 16, 16, __nv_bfloat16, wmma::col_major> bf[2];
                #pragma unroll
                for (int mi = 0; mi < 4; mi++)
                    wmma::load_matrix_sync(af[mi], asPtr(st, wm * 64 + mi * 16, kk), FLDS);
                #pragma unroll
                for (int ni = 0; ni < 2; ni++)
                    wmma::load_matrix_sync(bf[ni], bsPtr(st, wn * 32 + ni * 16, kk), FLDS);
                #pragma unroll
                for (int mi = 0; mi < 4; mi++)
                    #pragma unroll
                    for (int ni = 0; ni < 2; ni++)
                        wmma::mma_sync(acc[mi][ni], af[mi], bf[ni], acc[mi][ni]);
            }
            __syncthreads();
        }
        float* mystg = stg + warp * 16 * 20;
        #pragma unroll
        for (int mi = 0; mi < 4; mi++)
            #pragma unroll
            for (int ni = 0; ni < 2; ni++) {
                wmma::store_matrix_sync(mystg, acc[mi][ni], 20, wmma::mem_row_major);
                __syncwarp();
                int r = lane >> 1; int cb = (lane & 1) * 8;
                int grow = wm * 64 + mi * 16 + r;
                int gcol = wn * 32 + ni * 16 + cb;
                float base = xs_s[grow];
                float vals[8];
                #pragma unroll
                for (int c = 0; c < 8; c++)
                    vals[c] = fmaf(-2.0f, mystg[r * 20 + cb + c], base + bs_s[gcol + c]);
                const int row = row0 + grow;
                const float thv = thr[row];
                int cnt = 0;
                #pragma unroll
                for (int c = 0; c < 8; c++) if (vals[c] <= thv) cnt++;
                unsigned idx = 0;
                if (cnt > 0) idx = atomicAdd(&ccnt[row], (unsigned)cnt);
                #pragma unroll
                for (int c = 0; c < 8; c++) {
                    if (vals[c] <= thv) {
                        if (idx < CAP) cand[(size_t)row * CAP + idx] = vals[c];
                        idx++;
                    }
                }
                __syncwarp();
            }
        __syncthreads();
    }
#endif
}

// ---------------------------------------------------------------------------
// Final selection (uniform-trip-count radix + gather + sort)
// ---------------------------------------------------------------------------
#define FK_SBUF  0
#define FK_HIST  (CAP * 4)
#define FK_BUF2  (FK_HIST + 4096 * 4)
#define FK_CSUM  (FK_BUF2 + 2048 * 4)
#define FK_TOTAL (FK_CSUM + 256 * 4)

__global__ void __launch_bounds__(256) final_kernel(
    const float* __restrict__ cand,
    const unsigned* __restrict__ ccnt,
    float* __restrict__ out) {
    extern __shared__ __align__(16) char fsm[];
    float* sbuf = (float*)(fsm + FK_SBUF);
    uint32_t* hist = (uint32_t*)(fsm + FK_HIST);
    float* buf2 = (float*)(fsm + FK_BUF2);
    uint32_t* csum = (uint32_t*)(fsm + FK_CSUM);
    __shared__ uint32_t sh_bin, sh_less, sh_cnt;

    const int t = blockIdx.x;
    const int tid = threadIdx.x;
    const int lane = tid & 31;
    const float INF = __int_as_float(0x7F800000);

    int n = (int)min(ccnt[t], (unsigned)CAP);
    for (int i = tid; i < n; i += 256)
        sbuf[i] = cand[(size_t)t * CAP + i];
    if (n < KSEL) {
        for (int i = n + tid; i < KSEL; i += 256) sbuf[i] = INF;
        n = KSEL;
    }
    __syncthreads();

    const int n_pad = (n + 255) & ~255;

    unsigned P = 0;
    int lessTotal = 0;
    const int shifts[2] = {20, 8};
    for (int level = 0; level < 2; level++) {
        const int shift = shifts[level];
        const int prevShift = (level > 0) ? shifts[level - 1] : 32;
        for (int i = tid; i < 4096; i += 256) hist[i] = 0;
        __syncthreads();
        for (int base = 0; base < n_pad; base += 256) {
            int i = base + tid;
            int bin = -1;
            if (i < n) {
                unsigned key = flip_key(sbuf[i]);
                bool match = (level == 0) || ((key >> prevShift) == P);
                if (match) bin = (int)((key >> shift) & 4095u);
            }
            unsigned grp = __match_any_sync(0xFFFFFFFFu, bin);
            int leader = __ffs(grp) - 1;
            if (lane == leader && bin >= 0)
                atomicAdd(&hist[bin], __popc(grp));
        }
        __syncthreads();

        unsigned mysum = 0;
        #pragma unroll
        for (int b = 0; b < 16; b++) mysum += hist[tid * 16 + b];
        csum[tid] = mysum;
        __syncthreads();
        #pragma unroll
        for (int off = 1; off < 256; off <<= 1) {
            unsigned v = (tid >= off) ? csum[tid - off] : 0u;
            __syncthreads();
            csum[tid] += v;
            __syncthreads();
        }
        unsigned incl = csum[tid];
        unsigned excl = incl - mysum;
        const unsigned R = (unsigned)(KSEL - lessTotal);
        if (excl < R && R <= incl) {
            unsigned cum = excl;
            for (int b = 0; b < 16; b++) {
                unsigned c = hist[tid * 16 + b];
                if (cum + c >= R) {
                    sh_bin = tid * 16 + b;
                    sh_less = cum;
                    break;
                }
                cum += c;
            }
        }
        __syncthreads();
        P = (level == 0) ? sh_bin : ((P << 12) | sh_bin);
        lessTotal += (int)sh_less;
        __syncthreads();
    }

    if (tid == 0) sh_cnt = 0;
    __syncthreads();
    for (int i = tid; i < n; i += 256) {
        float d = sbuf[i];
        if ((flip_key(d) >> 8) <= P) {
            unsigned p = atomicAdd(&sh_cnt, 1u);
            if (p < 2048) buf2[p] = d;
        }
    }
    __syncthreads();
    int cnt = (int)sh_cnt;

    float* sortbuf;
    int sn;
    if (cnt <= 2048) { sortbuf = buf2; sn = cnt; }
    else             { sortbuf = sbuf; sn = n; }

    int m = KSEL;
    while (m < sn) m <<= 1;
    for (int i = sn + tid; i < m; i += 256) sortbuf[i] = INF;
    __syncthreads();

    for (int ksz = 2; ksz <= m; ksz <<= 1) {
        for (int j2 = ksz >> 1; j2 > 0; j2 >>= 1) {
            for (int i = tid; i < m; i += 256) {
                int ixj = i ^ j2;
                if (ixj > i) {
                    float a = sortbuf[i];
                    float b = sortbuf[ixj];
                    bool up = ((i & ksz) == 0);
                    if ((a > b) == up) { sortbuf[i] = b; sortbuf[ixj] = a; }
                }
            }
            __syncthreads();
        }
    }

    if (tid < KSEL) out[(size_t)t * KSEL + tid] = sortbuf[tid];
}

// ---------------------------------------------------------------------------
// Host: tensor map creation via driver entry point
// ---------------------------------------------------------------------------
typedef CUresult (*PFN_tmapEncode)(
    CUtensorMap*, CUtensorMapDataType, cuuint32_t, void*,
    const cuuint64_t*, const cuuint64_t*, const cuuint32_t*, const cuuint32_t*,
    CUtensorMapInterleave, CUtensorMapSwizzle, CUtensorMapL2promotion,
    CUtensorMapFloatOOBfill);

static PFN_tmapEncode get_encoder() {
    static PFN_tmapEncode fn = nullptr;
    if (!fn) {
        void* p = nullptr;
        cudaDriverEntryPointQueryResult st;
        cudaGetDriverEntryPoint("cuTensorMapEncodeTiled", &p, cudaEnableDefault, &st);
        fn = (PFN_tmapEncode)p;
    }
    return fn;
}

static void make_map(CUtensorMap* map, void* ptr, uint64_t rows, uint32_t box_h) {
    cuuint64_t dims[2] = {DMODEL, rows};
    cuuint64_t strides[1] = {DMODEL * 2};
    cuuint32_t box[2] = {BKT, box_h};
    cuuint32_t elemstr[2] = {1, 1};
    get_encoder()(map, CU_TENSOR_MAP_DATA_TYPE_BFLOAT16, 2, ptr,
                  dims, strides, box, elemstr,
                  CU_TENSOR_MAP_INTERLEAVE_NONE, CU_TENSOR_MAP_SWIZZLE_128B,
                  CU_TENSOR_MAP_L2_PROMOTION_L2_128B,
                  CU_TENSOR_MAP_FLOAT_OOB_FILL_NONE);
}

// ---------------------------------------------------------------------------
// Launch
// ---------------------------------------------------------------------------
extern "C" void kernel_launch(void* const* d_in, const int* in_sizes, int n_in,
                              void* d_out, int out_size) {
    const float* x = (const float*)d_in[0];
    const float* w = (const float*)d_in[1];
    float* out = (float*)d_out;

    float *scr, *xsq, *bsq, *bsq_s, *thr;
    __nv_bfloat16 *xb, *wb, *ws;
    unsigned* ccnt;
    cudaGetSymbolAddress((void**)&scr, g_scr);
    cudaGetSymbolAddress((void**)&xsq, g_xsq);
    cudaGetSymbolAddress((void**)&bsq, g_bsq);
    cudaGetSymbolAddress((void**)&bsq_s, g_bsq_s);
    cudaGetSymbolAddress((void**)&thr, g_thr);
    cudaGetSymbolAddress((void**)&xb, g_xb);
    cudaGetSymbolAddress((void**)&wb, g_wb);
    cudaGetSymbolAddress((void**)&ws, g_ws);
    cudaGetSymbolAddress((void**)&ccnt, g_ccnt);

    float* cand = scr;
    float* dist_s = scr + (size_t)TOKENS * CAP;

    CUtensorMap tma_x, tma_w, tma_ws;
    make_map(&tma_x, xb, TOKENS, BM);
    make_map(&tma_w, wb, VOCAB, BN);
    make_map(&tma_ws, ws, NSAMP, BN);

    prep_kernel<<<TOKENS, 256>>>(x, xb, xsq);
    prep_kernel<<<VOCAB, 256>>>(w, wb, bsq);
    gather_kernel<<<NSAMP, 256>>>(wb, bsq, ws, bsq_s, ccnt);

    cudaFuncSetAttribute(gemm_sample_kernel,
                         cudaFuncAttributeMaxDynamicSharedMemorySize, SM_TOTAL);
    cudaFuncSetAttribute(gemm_persist_kernel,
                         cudaFuncAttributeMaxDynamicSharedMemorySize, SM_TOTAL);
    cudaFuncSetAttribute(final_kernel,
                         cudaFuncAttributeMaxDynamicSharedMemorySize, FK_TOTAL);

    // Sample GEMM: [4096 x 256]
    gemm_sample_kernel<<<dim3(TOKENS / BM, NSAMP / BN), 256, SM_TOTAL>>>(
        tma_x, tma_ws, xb, ws, xsq, bsq_s, dist_s, NSAMP);

    thr_kernel<<<TOKENS, 256>>>(dist_s, thr);

    // Persistent big GEMM: candidate push (quad-buffered accumulators)
    gemm_persist_kernel<<<dim3(TOKENS / BM, GRIDY), 256, SM_TOTAL>>>(
        tma_x, tma_w, xb, wb, xsq, bsq, thr, cand, ccnt);

    final_kernel<<<TOKENS, 256, FK_TOTAL>>>(cand, ccnt, out);
}

// round 17
// speedup vs baseline: 1.0649x; 1.0058x over previous
#include <cuda_runtime.h>
#include <cuda.h>
#include <cuda_bf16.h>
#include <mma.h>
#include <cstdint>

#define TOKENS 4096
#define DMODEL 1024
#define VOCAB  32000
#define KSEL   128
#define NSAMP  256
#define SSTRIDE 125
#define THR_RANK 14
#define CAP 8192

#if defined(__CUDA_ARCH_FEAT_SM103_ALL) || defined(__CUDA_ARCH_FEAT_SM100_ALL) || \
    defined(__CUDA_ARCH_FEAT_SM101_ALL) || defined(__CUDA_ARCH_SPECIFIC__) || \
    defined(__CUDA_ARCH_FAMILY_SPECIFIC__)
#define TC_PATH 1
#else
#define TC_PATH 0
#endif

// ------- GEMM tiling: 128x128 tile, 3-stage smem ring, persistent CTAs -------
#define BM 128
#define BN 128
#define BKT 64                     // K elems per smem tile (128B bf16 rows)
#define NKT (DMODEL / BKT)         // 16
#define STAGES 3
#define ATILEB (BM * 128)          // 16KB
#define BTILEB (BN * 128)          // 16KB
#define STAGEB (ATILEB + BTILEB)   // 32KB
#define NCOLT (VOCAB / BN)         // 250 col tiles
#define GRIDY 9                    // 32*9 = 288 persistent CTAs (144 clusters)
#define NACC 4                     // TMEM accumulator ring depth

#define SM_XS     (STAGES * STAGEB)          // 98304
#define SM_BS     (SM_XS + 512)              // bs ring: 4 x 128 floats
#define SM_TMEMP  (SM_BS + 2048)
#define SM_MBAR   (SM_TMEMP + 16)
// mbar: free[3]@0,8,16  full[3]@24,32,40  done[4]@48..72  epi_free[4]@80..104
#define SM_TOTAL  (SM_MBAR + 128)            // ~100.6KB -> 2 CTAs/SM

#define MMA_IDESC ((1u<<4)|(1u<<7)|(1u<<10)|((BN/8u)<<17)|((BM/16u)<<24))

#define FBK 32
#define FLDS (FBK + 8)

// Device scratch
static __device__ float g_scr[(size_t)TOKENS * CAP + (size_t)TOKENS * NSAMP];
static __device__ __align__(1024) __nv_bfloat16 g_xb[(size_t)TOKENS * DMODEL];
static __device__ __align__(1024) __nv_bfloat16 g_wb[(size_t)VOCAB * DMODEL];
static __device__ __align__(1024) __nv_bfloat16 g_ws[(size_t)NSAMP * DMODEL];
static __device__ float g_xsq[TOKENS];
static __device__ float g_bsq[VOCAB];
static __device__ float g_bsq_s[NSAMP];
static __device__ float g_thr[TOKENS];
static __device__ unsigned g_ccnt[TOKENS];

// ---------------------------------------------------------------------------
// PTX helpers
// ---------------------------------------------------------------------------
__device__ __forceinline__ uint32_t smem_u32(const void* p) {
    uint32_t a;
    asm("{ .reg .u64 t; cvta.to.shared.u64 t, %1; cvt.u32.u64 %0, t; }" : "=r"(a) : "l"(p));
    return a;
}
__device__ __forceinline__ void cp_async16(uint32_t s, const void* g) {
    asm volatile("cp.async.cg.shared.global [%0], [%1], 16;\n" :: "r"(s), "l"(g));
}
__device__ __forceinline__ void cp_commit() { asm volatile("cp.async.commit_group;\n" ::); }
template <int N>
__device__ __forceinline__ void cp_wait() { asm volatile("cp.async.wait_group %0;\n" :: "n"(N)); }

#if TC_PATH
__device__ __forceinline__ bool elect_one() {
    uint32_t pred;
    asm volatile("{\n\t.reg .pred p;\n\telect.sync _|p, 0xFFFFFFFF;\n\t"
                 "selp.b32 %0, 1, 0, p;\n\t}" : "=r"(pred));
    return pred != 0;
}
__device__ __forceinline__ uint32_t ctarank() {
    uint32_t r;
    asm("mov.u32 %0, %%cluster_ctarank;" : "=r"(r));
    return r;
}
__device__ __forceinline__ void cluster_sync() {
    asm volatile("barrier.cluster.arrive.aligned;" ::: "memory");
    asm volatile("barrier.cluster.wait.aligned;" ::: "memory");
}
__device__ __forceinline__ void mbar_init(uint32_t a, uint32_t cnt) {
    asm volatile("mbarrier.init.shared.b64 [%0], %1;" :: "r"(a), "r"(cnt) : "memory");
}
__device__ __forceinline__ void mbar_inval(uint32_t a) {
    asm volatile("mbarrier.inval.shared.b64 [%0];" :: "r"(a) : "memory");
}
__device__ __forceinline__ void mbar_wait(uint32_t a, uint32_t parity) {
    uint32_t done;
    asm volatile("{\n\t.reg .pred p;\n\t"
                 "mbarrier.try_wait.parity.acquire.cta.shared::cta.b64 p, [%1], %2;\n\t"
                 "selp.b32 %0, 1, 0, p;\n\t}"
                 : "=r"(done) : "r"(a), "r"(parity) : "memory");
    if (!done) {
        asm volatile("{\n\t.reg .pred P1;\n\t"
                     "WL_%=:\n\t"
                     "mbarrier.try_wait.parity.acquire.cta.shared::cta.b64 P1, [%0], %1, 0x989680;\n\t"
                     "@P1 bra.uni WD_%=;\n\t"
                     "bra.uni WL_%=;\n\t"
                     "WD_%=:\n\t}" :: "r"(a), "r"(parity) : "memory");
    }
}
__device__ __forceinline__ void mbar_arrive(uint32_t a) {
    asm volatile("mbarrier.arrive.release.cta.shared::cta.b64 _, [%0];" :: "r"(a) : "memory");
}
__device__ __forceinline__ void mbar_expect_tx(uint32_t a, uint32_t bytes) {
    asm volatile("mbarrier.arrive.expect_tx.shared.b64 _, [%0], %1;"
                 :: "r"(a), "r"(bytes) : "memory");
}
__device__ __forceinline__ void tma_load_2d(uint32_t dst, const void* map,
                                            int cx, int cy, uint32_t mbar) {
    asm volatile("cp.async.bulk.tensor.2d.shared::cta.global.tile.mbarrier::complete_tx::bytes "
                 "[%0], [%1, {%2, %3}], [%4];"
                 :: "r"(dst), "l"(map), "r"(cx), "r"(cy), "r"(mbar) : "memory");
}
__device__ __forceinline__ void tma_load_2d_mcast(uint32_t dst, const void* map,
                                                  int cx, int cy, uint32_t mbar,
                                                  uint16_t mask) {
    asm volatile("cp.async.bulk.tensor.2d.shared::cluster.global.tile.mbarrier::complete_tx::bytes.multicast::cluster "
                 "[%0], [%1, {%2, %3}], [%4], %5;"
                 :: "r"(dst), "l"(map), "r"(cx), "r"(cy), "r"(mbar), "h"(mask) : "memory");
}
__device__ __forceinline__ void tmem_alloc(uint32_t smem_res, uint32_t ncols) {
    asm volatile("tcgen05.alloc.cta_group::1.sync.aligned.shared::cta.b32 [%0], %1;"
                 :: "r"(smem_res), "r"(ncols) : "memory");
}
__device__ __forceinline__ void tmem_dealloc(uint32_t tmem, uint32_t ncols) {
    asm volatile("tcgen05.dealloc.cta_group::1.sync.aligned.b32 %0, %1;" :: "r"(tmem), "r"(ncols));
}
__device__ __forceinline__ void tmem_relinquish() {
    asm volatile("tcgen05.relinquish_alloc_permit.cta_group::1.sync.aligned;");
}
__device__ __forceinline__ void tc_commit(uint32_t mbar) {
    asm volatile("tcgen05.commit.cta_group::1.mbarrier::arrive::one.shared::cluster.b64 [%0];"
                 :: "r"(mbar) : "memory");
}
__device__ __forceinline__ void tc_commit_mcast(uint32_t mbar, uint16_t mask) {
    asm volatile("tcgen05.commit.cta_group::1.mbarrier::arrive::one.shared::cluster.multicast::cluster.b64 [%0], %1;"
                 :: "r"(mbar), "h"(mask) : "memory");
}
__device__ __forceinline__ void tc_fence_after() {
    asm volatile("tcgen05.fence::after_thread_sync;" ::: "memory");
}
__device__ __forceinline__ void tc_fence_before() {
    asm volatile("tcgen05.fence::before_thread_sync;" ::: "memory");
}
__device__ __forceinline__ void tc_wait_ld() {
    asm volatile("tcgen05.wait::ld.sync.aligned;" ::: "memory");
}
__device__ __forceinline__ void mma_f16_ss(uint32_t d, uint64_t a, uint64_t b,
                                           uint32_t idesc, uint32_t en) {
    asm volatile("{\n\t.reg .pred p;\n\tsetp.ne.u32 p, %4, 0;\n\t"
                 "tcgen05.mma.cta_group::1.kind::f16 [%0], %1, %2, %3, {%5, %5, %5, %5}, p;\n\t}"
                 :: "r"(d), "l"(a), "l"(b), "r"(idesc), "r"(en), "r"(0u) : "memory");
}
__device__ __forceinline__ void ldtm_x32(uint32_t* r, uint32_t addr) {
    asm volatile("tcgen05.ld.sync.aligned.32x32b.x32.b32 "
                 "{%0, %1, %2, %3, %4, %5, %6, %7, "
                 " %8, %9, %10, %11, %12, %13, %14, %15, "
                 " %16, %17, %18, %19, %20, %21, %22, %23, "
                 " %24, %25, %26, %27, %28, %29, %30, %31}, [%32];"
                 : "=r"(r[0]), "=r"(r[1]), "=r"(r[2]), "=r"(r[3]),
                   "=r"(r[4]), "=r"(r[5]), "=r"(r[6]), "=r"(r[7]),
                   "=r"(r[8]), "=r"(r[9]), "=r"(r[10]), "=r"(r[11]),
                   "=r"(r[12]), "=r"(r[13]), "=r"(r[14]), "=r"(r[15]),
                   "=r"(r[16]), "=r"(r[17]), "=r"(r[18]), "=r"(r[19]),
                   "=r"(r[20]), "=r"(r[21]), "=r"(r[22]), "=r"(r[23]),
                   "=r"(r[24]), "=r"(r[25]), "=r"(r[26]), "=r"(r[27]),
                   "=r"(r[28]), "=r"(r[29]), "=r"(r[30]), "=r"(r[31])
                 : "r"(addr));
}
__device__ __forceinline__ uint64_t make_desc(uint32_t addr) {
    const uint64_t base = (uint64_t(2) << 61) | (uint64_t(1) << 46)
                        | (uint64_t(64) << 32) | (uint64_t(1) << 16);
    return base | ((uint64_t)(addr >> 4) & 0x3FFF);
}
#endif  // TC_PATH

__device__ __forceinline__ unsigned int flip_key(float f) {
    unsigned int u = __float_as_uint(f);
    return u ^ ((u & 0x80000000u) ? 0xFFFFFFFFu : 0x80000000u);
}

// ---------------------------------------------------------------------------
// Fused fp32->bf16 convert + row squared-norm
// ---------------------------------------------------------------------------
__global__ void prep_kernel(const float* __restrict__ src,
                            __nv_bfloat16* __restrict__ dst,
                            float* __restrict__ sq) {
    __shared__ float warp_sums[8];
    const int row = blockIdx.x;
    const int tid = threadIdx.x;
    const float* s = src + (size_t)row * DMODEL;
    __nv_bfloat16* d = dst + (size_t)row * DMODEL;

    float acc = 0.f;
    int j = tid * 4;
    {
        float4 v = *(const float4*)&s[j];
        acc += v.x * v.x + v.y * v.y + v.z * v.z + v.w * v.w;
        __nv_bfloat162 lo = __floats2bfloat162_rn(v.x, v.y);
        __nv_bfloat162 hi = __floats2bfloat162_rn(v.z, v.w);
        uint2 p; p.x = *(uint32_t*)&lo; p.y = *(uint32_t*)&hi;
        *(uint2*)&d[j] = p;
    }
    #pragma unroll
    for (int off = 16; off > 0; off >>= 1)
        acc += __shfl_xor_sync(0xFFFFFFFFu, acc, off);
    if ((tid & 31) == 0) warp_sums[tid >> 5] = acc;
    __syncthreads();
    if (tid == 0) {
        float total = 0.f;
        #pragma unroll
        for (int w = 0; w < 8; w++) total += warp_sums[w];
        sq[row] = total;
    }
}

__global__ void gather_kernel(const __nv_bfloat16* __restrict__ wb,
                              const float* __restrict__ bsq,
                              __nv_bfloat16* __restrict__ ws,
                              float* __restrict__ bsq_s,
                              unsigned* __restrict__ ccnt) {
    const int s = blockIdx.x;
    const int tid = threadIdx.x;
    const int src = s * SSTRIDE;
    ((uint2*)(ws + (size_t)s * DMODEL))[tid] =
        ((const uint2*)(wb + (size_t)src * DMODEL))[tid];
    if (tid == 0) bsq_s[s] = bsq[src];
    if (s < TOKENS / 256) ccnt[s * 256 + tid] = 0;
}

__global__ void thr_kernel(const float* __restrict__ dist_s,
                           float* __restrict__ thr) {
    __shared__ float samp[NSAMP];
    const int t = blockIdx.x;
    const int tid = threadIdx.x;
    samp[tid] = dist_s[(size_t)t * NSAMP + tid];
    __syncthreads();
    for (int k = 2; k <= NSAMP; k <<= 1) {
        for (int j = k >> 1; j > 0; j >>= 1) {
            int ixj = tid ^ j;
            if (ixj > tid) {
                float a = samp[tid], b = samp[ixj];
                bool up = ((tid & k) == 0);
                if ((a > b) == up) { samp[tid] = b; samp[ixj] = a; }
            }
            __syncthreads();
        }
    }
    if (tid == 0) thr[t] = samp[THR_RANK];
}

// ---------------------------------------------------------------------------
// Sample GEMM (non-persistent): writes dist matrix.
// ---------------------------------------------------------------------------
__global__ void __launch_bounds__(256)
gemm_sample_kernel(const __grid_constant__ CUtensorMap tma_a,
                   const __grid_constant__ CUtensorMap tma_b,
                   const __nv_bfloat16* __restrict__ A,
                   const __nv_bfloat16* __restrict__ B,
                   const float* __restrict__ xsq,
                   const float* __restrict__ bsq,
                   float* __restrict__ C, int ncols) {
    extern __shared__ __align__(1024) char sm[];
    const int tid = threadIdx.x;
    const int warp = tid >> 5;
    const int row0 = blockIdx.x * BM;
    const int col0 = blockIdx.y * BN;

#if TC_PATH
    const uint32_t smem_base = smem_u32(sm);
    float* xs_s = (float*)(sm + SM_XS);
    float* bs_s = (float*)(sm + SM_BS);
    const uint32_t mb_free0 = smem_base + SM_MBAR;
    const uint32_t mb_full0 = smem_base + SM_MBAR + 24;
    const uint32_t mb_done  = smem_base + SM_MBAR + 48;

    if (warp == 0) { tmem_alloc(smem_base + SM_TMEMP, 128); tmem_relinquish(); }
    if (tid == 0) {
        #pragma unroll
        for (int s = 0; s < STAGES; s++) {
            mbar_init(mb_free0 + s * 8, 1);
            mbar_init(mb_full0 + s * 8, 1);
        }
        mbar_init(mb_done, 1);
    }
    if (tid < BM) xs_s[tid] = xsq[row0 + tid];
    else if (tid >= 128 && tid < 256) bs_s[tid - 128] = bsq[col0 + tid - 128];
    __syncthreads();
    uint32_t tmem;
    asm volatile("ld.shared.b32 %0, [%1];" : "=r"(tmem) : "r"(smem_base + SM_TMEMP));

    if (warp == 1 && elect_one()) {
        for (int kt = 0; kt < NKT; kt++) {
            const int s = kt % STAGES;
            const int w = kt / STAGES;
            mbar_wait(mb_free0 + s * 8, (w & 1) ^ 1);
            const uint32_t stage_base = smem_base + s * STAGEB;
            mbar_expect_tx(mb_full0 + s * 8, STAGEB);
            tma_load_2d(stage_base, &tma_a, kt * BKT, row0, mb_full0 + s * 8);
            tma_load_2d(stage_base + ATILEB, &tma_b, kt * BKT, col0, mb_full0 + s * 8);
        }
    } else if (warp == 0 && elect_one()) {
        for (int kt = 0; kt < NKT; kt++) {
            const int s = kt % STAGES;
            const int w = kt / STAGES;
            mbar_wait(mb_full0 + s * 8, w & 1);
            const uint32_t stage_base = smem_base + s * STAGEB;
            uint64_t ad = make_desc(stage_base);
            uint64_t bd = make_desc(stage_base + ATILEB);
            #pragma unroll
            for (int k = 0; k < 4; k++) {
                uint32_t en = (kt > 0 || k > 0) ? 1u : 0u;
                mma_f16_ss(tmem, ad + k * 2, bd + k * 2, MMA_IDESC, en);
            }
            tc_commit((kt == NKT - 1) ? mb_done : (mb_free0 + s * 8));
        }
    }

    mbar_wait(mb_done, 0);
    tc_fence_after();

    if (tid < 128) {
        const int row = row0 + tid;
        const float base = xs_s[tid];
        #pragma unroll
        for (int c4 = 0; c4 < 4; c4++) {
            uint32_t regs[32];
            ldtm_x32(regs, tmem + c4 * 32);
            tc_wait_ld();
            #pragma unroll
            for (int j = 0; j < 32; j++) {
                float dist = fmaf(-2.0f, __uint_as_float(regs[j]),
                                  base + bs_s[c4 * 32 + j]);
                C[(size_t)row * ncols + col0 + c4 * 32 + j] = dist;
            }
        }
        tc_fence_before();
    }

    __syncthreads();
    if (tid == 0) {
        #pragma unroll
        for (int s = 0; s < STAGES; s++) {
            mbar_inval(mb_free0 + s * 8);
            mbar_inval(mb_full0 + s * 8);
        }
        mbar_inval(mb_done);
    }
    __syncthreads();
    if (warp == 0) tmem_dealloc(tmem, 128);

#else
    using namespace nvcuda;
    __nv_bfloat16* AsBase = (__nv_bfloat16*)sm;
    __nv_bfloat16* BsBase = (__nv_bfloat16*)(sm + 2 * BM * FLDS * 2);
    float* xs_s = (float*)(sm + 4 * BM * FLDS * 2);
    float* bs_s = xs_s + BM;
    float* stg = (float*)sm;
    const int lane = tid & 31;
    const int wm = warp & 1;
    const int wn = warp >> 1;
    if (tid < BM) xs_s[tid] = xsq[row0 + tid];
    if (tid < BN) bs_s[tid] = bsq[col0 + tid];
    __syncthreads();
    wmma::fragment<wmma::accumulator, 16, 16, 16, float> acc[4][2];
    #pragma unroll
    for (int i = 0; i < 4; i++)
        #pragma unroll
        for (int j = 0; j < 2; j++) wmma::fill_fragment(acc[i][j], 0.0f);
    auto asPtr = [&](int st, int r, int c) { return AsBase + (size_t)st * BM * FLDS + r * FLDS + c; };
    auto bsPtr = [&](int st, int r, int c) { return BsBase + (size_t)st * BN * FLDS + r * FLDS + c; };
    auto issue_loads = [&](int st, int k0) {
        #pragma unroll
        for (int i = 0; i < 2; i++) {
            int c = tid + i * 256; int r = c >> 2; int cc = (c & 3) * 8;
            cp_async16(smem_u32(asPtr(st, r, cc)), A + (size_t)(row0 + r) * DMODEL + k0 + cc);
        }
        #pragma unroll
        for (int i = 0; i < 2; i++) {
            int c = tid + i * 256; int r = c >> 2; int cc = (c & 3) * 8;
            cp_async16(smem_u32(bsPtr(st, r, cc)), B + (size_t)(col0 + r) * DMODEL + k0 + cc);
        }
        cp_commit();
    };
    issue_loads(0, 0);
    const int NTF = DMODEL / FBK;
    for (int kt = 0; kt < NTF; kt++) {
        int st = kt & 1;
        if (kt + 1 < NTF) { issue_loads((kt + 1) & 1, (kt + 1) * FBK); cp_wait<1>(); }
        else cp_wait<0>();
        __syncthreads();
        #pragma unroll
        for (int kk = 0; kk < FBK; kk += 16) {
            wmma::fragment<wmma::matrix_a, 16, 16, 16, __nv_bfloat16, wmma::row_major> af[4];
            wmma::fragment<wmma::matrix_b, 16, 16, 16, __nv_bfloat16, wmma::col_major> bf[2];
            #pragma unroll
            for (int mi = 0; mi < 4; mi++)
                wmma::load_matrix_sync(af[mi], asPtr(st, wm * 64 + mi * 16, kk), FLDS);
            #pragma unroll
            for (int ni = 0; ni < 2; ni++)
                wmma::load_matrix_sync(bf[ni], bsPtr(st, wn * 32 + ni * 16, kk), FLDS);
            #pragma unroll
            for (int mi = 0; mi < 4; mi++)
                #pragma unroll
                for (int ni = 0; ni < 2; ni++)
                    wmma::mma_sync(acc[mi][ni], af[mi], bf[ni], acc[mi][ni]);
        }
        __syncthreads();
    }
    float* mystg = stg + warp * 16 * 20;
    #pragma unroll
    for (int mi = 0; mi < 4; mi++)
        #pragma unroll
        for (int ni = 0; ni < 2; ni++) {
            wmma::store_matrix_sync(mystg, acc[mi][ni], 20, wmma::mem_row_major);
            __syncwarp();
            int r = lane >> 1; int cb = (lane & 1) * 8;
            int grow = wm * 64 + mi * 16 + r;
            int gcol = wn * 32 + ni * 16 + cb;
            float base = xs_s[grow];
            float* dst = &C[(size_t)(row0 + grow) * ncols + col0 + gcol];
            #pragma unroll
            for (int c = 0; c < 8; c++)
                dst[c] = fmaf(-2.0f, mystg[r * 20 + cb + c], base + bs_s[gcol + c]);
            __syncwarp();
        }
#endif
}

// ---------------------------------------------------------------------------
// Persistent big GEMM: 2-CTA clusters share B via TMA multicast.
// Rank 0 loads B once per kt (multicast to both CTAs); each CTA loads own A.
// free[s]: rank0 count=2 (own + rank1 mcast commit), rank1 count=1.
// ---------------------------------------------------------------------------
__global__ void __launch_bounds__(256) __cluster_dims__(2, 1, 1)
gemm_persist_kernel(const __grid_constant__ CUtensorMap tma_a,
                    const __grid_constant__ CUtensorMap tma_b,
                    const __nv_bfloat16* __restrict__ A,
                    const __nv_bfloat16* __restrict__ B,
                    const float* __restrict__ xsq,
                    const float* __restrict__ bsq,
                    const float* __restrict__ thr,
                    float* __restrict__ cand,
                    unsigned* __restrict__ ccnt) {
    extern __shared__ __align__(1024) char sm[];
    const int tid = threadIdx.x;
    const int warp = tid >> 5;
    const int row0 = blockIdx.x * BM;

#if TC_PATH
    const uint32_t smem_base = smem_u32(sm);
    const uint32_t rank = ctarank();
    float* xs_s = (float*)(sm + SM_XS);
    float* bs4 = (float*)(sm + SM_BS);
    const uint32_t mb_free0 = smem_base + SM_MBAR;        // +s*8
    const uint32_t mb_full0 = smem_base + SM_MBAR + 24;   // +s*8
    const uint32_t mb_done0 = smem_base + SM_MBAR + 48;   // +h*8
    const uint32_t mb_epi0  = smem_base + SM_MBAR + 80;   // +h*8

    if (warp == 0) { tmem_alloc(smem_base + SM_TMEMP, 512); tmem_relinquish(); }
    if (tid == 0) {
        #pragma unroll
        for (int s = 0; s < STAGES; s++) {
            mbar_init(mb_free0 + s * 8, rank == 0 ? 2 : 1);
            mbar_init(mb_full0 + s * 8, 1);
        }
        #pragma unroll
        for (int h = 0; h < NACC; h++) {
            mbar_init(mb_done0 + h * 8, 1);
            mbar_init(mb_epi0 + h * 8, 128);
        }
    }
    if (tid < BM) xs_s[tid] = xsq[row0 + tid];
    __syncthreads();
    cluster_sync();   // all mbarriers live before any multicast targets them
    uint32_t tmem;
    asm volatile("ld.shared.b32 %0, [%1];" : "=r"(tmem) : "r"(smem_base + SM_TMEMP));

    if (warp == 1 && elect_one()) {
        // ------- producer: own A always; rank0 also multicasts B -------
        int gkt = 0;
        for (int ct = blockIdx.y; ct < NCOLT; ct += GRIDY) {
            for (int kt = 0; kt < NKT; kt++, gkt++) {
                const int s = gkt % STAGES;
                const int w = gkt / STAGES;
                mbar_wait(mb_free0 + s * 8, (w & 1) ^ 1);
                const uint32_t stage_base = smem_base + s * STAGEB;
                mbar_expect_tx(mb_full0 + s * 8, STAGEB);
                tma_load_2d(stage_base, &tma_a, kt * BKT, row0, mb_full0 + s * 8);
                if (rank == 0)
                    tma_load_2d_mcast(stage_base + ATILEB, &tma_b, kt * BKT, ct * BN,
                                      mb_full0 + s * 8, 0x3);
            }
        }
    } else if (warp == 0 && elect_one()) {
        // ------- MMA driver -------
        int gkt = 0, ti = 0;
        for (int ct = blockIdx.y; ct < NCOLT; ct += GRIDY, ti++) {
            const int h = ti & (NACC - 1);
            const int u = ti / NACC;
            if (ti >= NACC) mbar_wait(mb_epi0 + h * 8, (u - 1) & 1);
            const uint32_t dtm = tmem + h * 128;
            for (int kt = 0; kt < NKT; kt++, gkt++) {
                const int s = gkt % STAGES;
                const int w = gkt / STAGES;
                mbar_wait(mb_full0 + s * 8, w & 1);
                const uint32_t stage_base = smem_base + s * STAGEB;
                uint64_t ad = make_desc(stage_base);
                uint64_t bd = make_desc(stage_base + ATILEB);
                #pragma unroll
                for (int k = 0; k < 4; k++) {
                    uint32_t en = (kt > 0 || k > 0) ? 1u : 0u;
                    mma_f16_ss(dtm, ad + k * 2, bd + k * 2, MMA_IDESC, en);
                }
                if (rank == 0) tc_commit(mb_free0 + s * 8);       // self only
                else           tc_commit_mcast(mb_free0 + s * 8, 0x3);  // both CTAs
                if (kt == NKT - 1) tc_commit(mb_done0 + h * 8);
            }
        }
    }

    // ------- epilogue: threads 128-255 -------
    if (tid >= 128) {
        const int e = tid - 128;
        const int row = row0 + e;
        const float base = xs_s[e];
        const float thv = thr[row];
        int ti = 0;
        for (int ct = blockIdx.y; ct < NCOLT; ct += GRIDY, ti++) {
            const int h = ti & (NACC - 1);
            const int u = ti / NACC;
            mbar_wait(mb_done0 + h * 8, u & 1);
            tc_fence_after();
            bs4[h * 128 + e] = bsq[ct * BN + e];
            asm volatile("bar.sync 1, 128;" ::: "memory");
            const uint32_t dtm = tmem + h * 128;
            const float* bs = &bs4[h * 128];

            uint32_t masks[4];
            int cnt = 0;
            #pragma unroll
            for (int c4 = 0; c4 < 4; c4++) {
                uint32_t regs[32];
                ldtm_x32(regs, dtm + c4 * 32);
                tc_wait_ld();
                uint32_t mask = 0;
                #pragma unroll
                for (int j = 0; j < 32; j++) {
                    float dist = fmaf(-2.0f, __uint_as_float(regs[j]),
                                      base + bs[c4 * 32 + j]);
                    if (dist <= thv) mask |= (1u << j);
                }
                masks[c4] = mask;
                cnt += __popc(mask);
            }
            unsigned idx = 0;
            if (cnt > 0) idx = atomicAdd(&ccnt[row], (unsigned)cnt);
            #pragma unroll
            for (int c4 = 0; c4 < 4; c4++) {
                uint32_t regs[32];
                ldtm_x32(regs, dtm + c4 * 32);
                tc_wait_ld();
                uint32_t mask = masks[c4];
                #pragma unroll
                for (int j = 0; j < 32; j++) {
                    if ((mask >> j) & 1u) {
                        float dist = fmaf(-2.0f, __uint_as_float(regs[j]),
                                          base + bs[c4 * 32 + j]);
                        if (idx < CAP) cand[(size_t)row * CAP + idx] = dist;
                        idx++;
                    }
                }
            }
            tc_fence_before();
            asm volatile("bar.sync 1, 128;" ::: "memory");
            mbar_arrive(mb_epi0 + h * 8);
        }
    }

    __syncthreads();
    cluster_sync();   // all cross-CTA arrivals landed before inval
    if (tid == 0) {
        #pragma unroll
        for (int s = 0; s < STAGES; s++) {
            mbar_inval(mb_free0 + s * 8);
            mbar_inval(mb_full0 + s * 8);
        }
        #pragma unroll
        for (int h = 0; h < NACC; h++) {
            mbar_inval(mb_done0 + h * 8);
            mbar_inval(mb_epi0 + h * 8);
        }
    }
    __syncthreads();
    if (warp == 0) tmem_dealloc(tmem, 512);
    cluster_sync();

#else  // ---------------- WMMA fallback: independent per-CTA loop ----------------
    using namespace nvcuda;
    __nv_bfloat16* AsBase = (__nv_bfloat16*)sm;
    __nv_bfloat16* BsBase = (__nv_bfloat16*)(sm + 2 * BM * FLDS * 2);
    float* xs_s = (float*)(sm + 4 * BM * FLDS * 2);
    float* bs_s = xs_s + BM;
    float* stg = (float*)sm;
    const int lane = tid & 31;
    const int wm = warp & 1;
    const int wn = warp >> 1;
    if (tid < BM) xs_s[tid] = xsq[row0 + tid];
    __syncthreads();

    for (int ct = blockIdx.y; ct < NCOLT; ct += GRIDY) {
        const int col0 = ct * BN;
        if (tid < BN) bs_s[tid] = bsq[col0 + tid];
        __syncthreads();
        wmma::fragment<wmma::accumulator, 16, 16, 16, float> acc[4][2];
        #pragma unroll
        for (int i = 0; i < 4; i++)
            #pragma unroll
            for (int j = 0; j < 2; j++) wmma::fill_fragment(acc[i][j], 0.0f);
        auto asPtr = [&](int st, int r, int c) { return AsBase + (size_t)st * BM * FLDS + r * FLDS + c; };
        auto bsPtr = [&](int st, int r, int c) { return BsBase + (size_t)st * BN * FLDS + r * FLDS + c; };
        auto issue_loads = [&](int st, int k0) {
            #pragma unroll
            for (int i = 0; i < 2; i++) {
                int c = tid + i * 256; int r = c >> 2; int cc = (c & 3) * 8;
                cp_async16(smem_u32(asPtr(st, r, cc)), A + (size_t)(row0 + r) * DMODEL + k0 + cc);
            }
            #pragma unroll
            for (int i = 0; i < 2; i++) {
                int c = tid + i * 256; int r = c >> 2; int cc = (c & 3) * 8;
                cp_async16(smem_u32(bsPtr(st, r, cc)), B + (size_t)(col0 + r) * DMODEL + k0 + cc);
            }
            cp_commit();
        };
        issue_loads(0, 0);
        const int NTF = DMODEL / FBK;
        for (int kt = 0; kt < NTF; kt++) {
            int st = kt & 1;
            if (kt + 1 < NTF) { issue_loads((kt + 1) & 1, (kt + 1) * FBK); cp_wait<1>(); }
            else cp_wait<0>();
            __syncthreads();
            #pragma unroll
            for (int kk = 0; kk < FBK; kk += 16) {
                wmma::fragment<wmma::matrix_a, 16, 16, 16, __nv_bfloat16, wmma::row_major> af[4];
                wmma::fragment<wmma::matrix_b, 16, 16, 16, __nv_bfloat16, wmma::col_major> bf[2];
                #pragma unroll
                for (int mi = 0; mi < 4; mi++)
                    wmma::load_matrix_sync(af[mi], asPtr(st, wm * 64 + mi * 16, kk), FLDS);
                #pragma unroll
                for (int ni = 0; ni < 2; ni++)
                    wmma::load_matrix_sync(bf[ni], bsPtr(st, wn * 32 + ni * 16, kk), FLDS);
                #pragma unroll
                for (int mi = 0; mi < 4; mi++)
                    #pragma unroll
                    for (int ni = 0; ni < 2; ni++)
                        wmma::mma_sync(acc[mi][ni], af[mi], bf[ni], acc[mi][ni]);
            }
            __syncthreads();
        }
        float* mystg = stg + warp * 16 * 20;
        #pragma unroll
        for (int mi = 0; mi < 4; mi++)
            #pragma unroll
            for (int ni = 0; ni < 2; ni++) {
                wmma::store_matrix_sync(mystg, acc[mi][ni], 20, wmma::mem_row_major);
                __syncwarp();
                int r = lane >> 1; int cb = (lane & 1) * 8;
                int grow = wm * 64 + mi * 16 + r;
                int gcol = wn * 32 + ni * 16 + cb;
                float base = xs_s[grow];
                float vals[8];
                #pragma unroll
                for (int c = 0; c < 8; c++)
                    vals[c] = fmaf(-2.0f, mystg[r * 20 + cb + c], base + bs_s[gcol + c]);
                const int row = row0 + grow;
                const float thv = thr[row];
                int cnt = 0;
                #pragma unroll
                for (int c = 0; c < 8; c++) if (vals[c] <= thv) cnt++;
                unsigned idx = 0;
                if (cnt > 0) idx = atomicAdd(&ccnt[row], (unsigned)cnt);
                #pragma unroll
                for (int c = 0; c < 8; c++) {
                    if (vals[c] <= thv) {
                        if (idx < CAP) cand[(size_t)row * CAP + idx] = vals[c];
                        idx++;
                    }
                }
                __syncwarp();
            }
        __syncthreads();
    }
#endif
}

// ---------------------------------------------------------------------------
// Final selection (uniform-trip-count radix + gather + sort)
// ---------------------------------------------------------------------------
#define FK_SBUF  0
#define FK_HIST  (CAP * 4)
#define FK_BUF2  (FK_HIST + 4096 * 4)
#define FK_CSUM  (FK_BUF2 + 2048 * 4)
#define FK_TOTAL (FK_CSUM + 256 * 4)

__global__ void __launch_bounds__(256) final_kernel(
    const float* __restrict__ cand,
    const unsigned* __restrict__ ccnt,
    float* __restrict__ out) {
    extern __shared__ __align__(16) char fsm[];
    float* sbuf = (float*)(fsm + FK_SBUF);
    uint32_t* hist = (uint32_t*)(fsm + FK_HIST);
    float* buf2 = (float*)(fsm + FK_BUF2);
    uint32_t* csum = (uint32_t*)(fsm + FK_CSUM);
    __shared__ uint32_t sh_bin, sh_less, sh_cnt;

    const int t = blockIdx.x;
    const int tid = threadIdx.x;
    const int lane = tid & 31;
    const float INF = __int_as_float(0x7F800000);

    int n = (int)min(ccnt[t], (unsigned)CAP);
    for (int i = tid; i < n; i += 256)
        sbuf[i] = cand[(size_t)t * CAP + i];
    if (n < KSEL) {
        for (int i = n + tid; i < KSEL; i += 256) sbuf[i] = INF;
        n = KSEL;
    }
    __syncthreads();

    const int n_pad = (n + 255) & ~255;

    unsigned P = 0;
    int lessTotal = 0;
    const int shifts[2] = {20, 8};
    for (int level = 0; level < 2; level++) {
        const int shift = shifts[level];
        const int prevShift = (level > 0) ? shifts[level - 1] : 32;
        for (int i = tid; i < 4096; i += 256) hist[i] = 0;
        __syncthreads();
        for (int base = 0; base < n_pad; base += 256) {
            int i = base + tid;
            int bin = -1;
            if (i < n) {
                unsigned key = flip_key(sbuf[i]);
                bool match = (level == 0) || ((key >> prevShift) == P);
                if (match) bin = (int)((key >> shift) & 4095u);
            }
            unsigned grp = __match_any_sync(0xFFFFFFFFu, bin);
            int leader = __ffs(grp) - 1;
            if (lane == leader && bin >= 0)
                atomicAdd(&hist[bin], __popc(grp));
        }
        __syncthreads();

        unsigned mysum = 0;
        #pragma unroll
        for (int b = 0; b < 16; b++) mysum += hist[tid * 16 + b];
        csum[tid] = mysum;
        __syncthreads();
        #pragma unroll
        for (int off = 1; off < 256; off <<= 1) {
            unsigned v = (tid >= off) ? csum[tid - off] : 0u;
            __syncthreads();
            csum[tid] += v;
            __syncthreads();
        }
        unsigned incl = csum[tid];
        unsigned excl = incl - mysum;
        const unsigned R = (unsigned)(KSEL - lessTotal);
        if (excl < R && R <= incl) {
            unsigned cum = excl;
            for (int b = 0; b < 16; b++) {
                unsigned c = hist[tid * 16 + b];
                if (cum + c >= R) {
                    sh_bin = tid * 16 + b;
                    sh_less = cum;
                    break;
                }
                cum += c;
            }
        }
        __syncthreads();
        P = (level == 0) ? sh_bin : ((P << 12) | sh_bin);
        lessTotal += (int)sh_less;
        __syncthreads();
    }

    if (tid == 0) sh_cnt = 0;
    __syncthreads();
    for (int i = tid; i < n; i += 256) {
        float d = sbuf[i];
        if ((flip_key(d) >> 8) <= P) {
            unsigned p = atomicAdd(&sh_cnt, 1u);
            if (p < 2048) buf2[p] = d;
        }
    }
    __syncthreads();
    int cnt = (int)sh_cnt;

    float* sortbuf;
    int sn;
    if (cnt <= 2048) { sortbuf = buf2; sn = cnt; }
    else             { sortbuf = sbuf; sn = n; }

    int m = KSEL;
    while (m < sn) m <<= 1;
    for (int i = sn + tid; i < m; i += 256) sortbuf[i] = INF;
    __syncthreads();

    for (int ksz = 2; ksz <= m; ksz <<= 1) {
        for (int j2 = ksz >> 1; j2 > 0; j2 >>= 1) {
            for (int i = tid; i < m; i += 256) {
                int ixj = i ^ j2;
                if (ixj > i) {
                    float a = sortbuf[i];
                    float b = sortbuf[ixj];
                    bool up = ((i & ksz) == 0);
                    if ((a > b) == up) { sortbuf[i] = b; sortbuf[ixj] = a; }
                }
            }
            __syncthreads();
        }
    }

    if (tid < KSEL) out[(size_t)t * KSEL + tid] = sortbuf[tid];
}

// ---------------------------------------------------------------------------
// Host: tensor map creation via driver entry point
// ---------------------------------------------------------------------------
typedef CUresult (*PFN_tmapEncode)(
    CUtensorMap*, CUtensorMapDataType, cuuint32_t, void*,
    const cuuint64_t*, const cuuint64_t*, const cuuint32_t*, const cuuint32_t*,
    CUtensorMapInterleave, CUtensorMapSwizzle, CUtensorMapL2promotion,
    CUtensorMapFloatOOBfill);

static PFN_tmapEncode get_encoder() {
    static PFN_tmapEncode fn = nullptr;
    if (!fn) {
        void* p = nullptr;
        cudaDriverEntryPointQueryResult st;
        cudaGetDriverEntryPoint("cuTensorMapEncodeTiled", &p, cudaEnableDefault, &st);
        fn = (PFN_tmapEncode)p;
    }
    return fn;
}

static void make_map(CUtensorMap* map, void* ptr, uint64_t rows, uint32_t box_h) {
    cuuint64_t dims[2] = {DMODEL, rows};
    cuuint64_t strides[1] = {DMODEL * 2};
    cuuint32_t box[2] = {BKT, box_h};
    cuuint32_t elemstr[2] = {1, 1};
    get_encoder()(map, CU_TENSOR_MAP_DATA_TYPE_BFLOAT16, 2, ptr,
                  dims, strides, box, elemstr,
                  CU_TENSOR_MAP_INTERLEAVE_NONE, CU_TENSOR_MAP_SWIZZLE_128B,
                  CU_TENSOR_MAP_L2_PROMOTION_L2_128B,
                  CU_TENSOR_MAP_FLOAT_OOB_FILL_NONE);
}

// ---------------------------------------------------------------------------
// Launch
// ---------------------------------------------------------------------------
extern "C" void kernel_launch(void* const* d_in, const int* in_sizes, int n_in,
                              void* d_out, int out_size) {
    const float* x = (const float*)d_in[0];
    const float* w = (const float*)d_in[1];
    float* out = (float*)d_out;

    float *scr, *xsq, *bsq, *bsq_s, *thr;
    __nv_bfloat16 *xb, *wb, *ws;
    unsigned* ccnt;
    cudaGetSymbolAddress((void**)&scr, g_scr);
    cudaGetSymbolAddress((void**)&xsq, g_xsq);
    cudaGetSymbolAddress((void**)&bsq, g_bsq);
    cudaGetSymbolAddress((void**)&bsq_s, g_bsq_s);
    cudaGetSymbolAddress((void**)&thr, g_thr);
    cudaGetSymbolAddress((void**)&xb, g_xb);
    cudaGetSymbolAddress((void**)&wb, g_wb);
    cudaGetSymbolAddress((void**)&ws, g_ws);
    cudaGetSymbolAddress((void**)&ccnt, g_ccnt);

    float* cand = scr;
    float* dist_s = scr + (size_t)TOKENS * CAP;

    CUtensorMap tma_x, tma_w, tma_ws;
    make_map(&tma_x, xb, TOKENS, BM);
    make_map(&tma_w, wb, VOCAB, BN);
    make_map(&tma_ws, ws, NSAMP, BN);

    prep_kernel<<<TOKENS, 256>>>(x, xb, xsq);
    prep_kernel<<<VOCAB, 256>>>(w, wb, bsq);
    gather_kernel<<<NSAMP, 256>>>(wb, bsq, ws, bsq_s, ccnt);

    cudaFuncSetAttribute(gemm_sample_kernel,
                         cudaFuncAttributeMaxDynamicSharedMemorySize, SM_TOTAL);
    cudaFuncSetAttribute(gemm_persist_kernel,
                         cudaFuncAttributeMaxDynamicSharedMemorySize, SM_TOTAL);
    cudaFuncSetAttribute(final_kernel,
                         cudaFuncAttributeMaxDynamicSharedMemorySize, FK_TOTAL);

    // Sample GEMM: [4096 x 256]
    gemm_sample_kernel<<<dim3(TOKENS / BM, NSAMP / BN), 256, SM_TOTAL>>>(
        tma_x, tma_ws, xb, ws, xsq, bsq_s, dist_s, NSAMP);

    thr_kernel<<<TOKENS, 256>>>(dist_s, thr);

    // Persistent big GEMM: 2-CTA clusters, multicast B
    gemm_persist_kernel<<<dim3(TOKENS / BM, GRIDY), 256, SM_TOTAL>>>(
        tma_x, tma_w, xb, wb, xsq, bsq, thr, cand, ccnt);

    final_kernel<<<TOKENS, 256, FK_TOTAL>>>(cand, ccnt, out);
}